// round 5
// baseline (speedup 1.0000x reference)
#include <cuda_runtime.h>
#include <math.h>

// ---------------- problem constants ----------------
#define B_   8
#define T_   256
#define MEL_ 128
#define D_   192
#define NC_  20
#define D2_  384
#define NT_  32     // theta updates  (chunk 8)
#define ND_  4      // delta updates  (chunk 64)
#define EPS_ 1e-5f
#define G_   128    // persistent grid (<= SM count, all co-resident)

// ---------------- scratch ----------------
__device__ float g_xp [B_*T_*D_];
__device__ float g_x1 [B_*T_*D_];
__device__ float g_x2 [B_*T_*D_];
__device__ float g_h  [B_*T_*D_];
__device__ float g_g2 [B_*T_*D_];
__device__ float g_x3 [B_*T_*D_];
__device__ float g_y  [B_*T_*D_];
__device__ float g_Kd [B_*ND_*D_];
__device__ float g_Vd [B_*ND_*D_];
__device__ float g_Qd [B_*ND_*D_];
__device__ float g_Ed [B_*ND_*D_];
__device__ float g_Kt [B_*NT_*D_];
__device__ float g_Vt [B_*NT_*D_];
__device__ float g_Qt [B_*NT_*D_];
__device__ float g_Et [B_*NT_*D_];
__device__ float g_Wao [D_*D_];
__device__ float g_bao [D_];
__device__ float g_Wkqd[D_*D_];
__device__ float g_Wkqt[D_*D_];

// barrier state
__device__ unsigned g_count;
__device__ unsigned g_gen;

__device__ __forceinline__ unsigned ldv(unsigned* p) {
    unsigned v; asm volatile("ld.volatile.u32 %0, [%1];" : "=r"(v) : "l"(p)); return v;
}
__device__ __forceinline__ void stv(unsigned* p, unsigned v) {
    asm volatile("st.volatile.u32 [%0], %1;" :: "l"(p), "r"(v));
}
// grid-wide sense barrier; all blocks of the (fully-resident) grid must call it.
__device__ __forceinline__ void gbar() {
    __syncthreads();
    if (threadIdx.x == 0) {
        __threadfence();
        unsigned gen = ldv(&g_gen);
        if (atomicAdd(&g_count, 1u) == (unsigned)gridDim.x - 1u) {
            stv(&g_count, 0u);
            __threadfence();
            atomicAdd(&g_gen, 1u);
        } else {
            while (ldv(&g_gen) == gen) __nanosleep(64);
        }
        __threadfence();
    }
    __syncthreads();
}

// coefficient c_d = LR*(a^{d+1}-e^{d+1})/(a-e), a=0.99, e=0.9
__device__ __forceinline__ float cdv(int d) {
    const float L2A = -0.014499569695115089f;   // log2(0.99)
    const float L2E = -0.152003093445049970f;   // log2(0.90)
    float n = (float)(d + 1);
    return (exp2f(n * L2A) - exp2f(n * L2E)) * (0.1f / 0.09f);
}

#define SH_SZ 7424
// ---------------- GEMM 64x64 tile, BK=16, 256 threads ----------------
__device__ void dev_gemm_tile(float* sh,
    const float* __restrict__ A, int ldA, const float* __restrict__ W, int ldW, bool transB,
    const float* __restrict__ bias, const float* __restrict__ res, float* __restrict__ C, int ldC,
    int m0, int n0, int K)
{
    float (*As)[68] = (float (*)[68])sh;
    float (*Ws)[64] = (float (*)[64])(sh + 16 * 68);
    int tid = threadIdx.x;
    int tx = tid & 15, ty = tid >> 4;
    float c[4][4] = {};
    for (int k0 = 0; k0 < K; k0 += 16) {
        {
            int arow = tid >> 2, acol = (tid & 3) * 4;
            float4 v = *(const float4*)&A[(size_t)(m0 + arow) * ldA + k0 + acol];
            As[acol + 0][arow] = v.x; As[acol + 1][arow] = v.y;
            As[acol + 2][arow] = v.z; As[acol + 3][arow] = v.w;
        }
        {
            int wrow = tid >> 4, wcol = (tid & 15) * 4;
            if (transB) {
#pragma unroll
                for (int u = 0; u < 4; u++)
                    Ws[wrow][wcol + u] = W[(size_t)(n0 + wcol + u) * ldW + k0 + wrow];
            } else {
                *(float4*)&Ws[wrow][wcol] = *(const float4*)&W[(size_t)(k0 + wrow) * ldW + n0 + wcol];
            }
        }
        __syncthreads();
#pragma unroll
        for (int kk = 0; kk < 16; kk++) {
            float4 af = *(const float4*)&As[kk][ty * 4];
            float4 bf = *(const float4*)&Ws[kk][tx * 4];
            float a4[4] = {af.x, af.y, af.z, af.w};
            float b4[4] = {bf.x, bf.y, bf.z, bf.w};
#pragma unroll
            for (int i = 0; i < 4; i++)
#pragma unroll
                for (int j = 0; j < 4; j++) c[i][j] = fmaf(a4[i], b4[j], c[i][j]);
        }
        __syncthreads();
    }
#pragma unroll
    for (int i = 0; i < 4; i++) {
        int row = m0 + ty * 4 + i, col = n0 + tx * 4;
        float4 o; float* po = &o.x;
#pragma unroll
        for (int j = 0; j < 4; j++) {
            float v = c[i][j];
            if (bias) v += bias[col + j];
            if (res)  v += res[(size_t)row * ldC + col + j];
            po[j] = v;
        }
        *(float4*)&C[(size_t)row * ldC + col] = o;
    }
}

// ---------------- GEMM tile with fused GLU+dw+BN+SiLU epilogue (K=192, W is [192][384]) ----------------
__device__ void dev_glu_tile(float* sh,
    const float* __restrict__ A, const float* __restrict__ W, const float* __restrict__ bias,
    const float* __restrict__ dw, const float* __restrict__ db,
    const float* __restrict__ bs, const float* __restrict__ bb,
    float* __restrict__ outp, int m0, int n0)
{
    float (*As)[68] = (float (*)[68])sh;
    float (*Wa)[64] = (float (*)[64])(sh + 16 * 68);
    float (*Wg)[64] = (float (*)[64])(sh + 16 * 68 + 16 * 64);
    int tid = threadIdx.x;
    int tx = tid & 15, ty = tid >> 4;
    float cA[4][4] = {}, cG[4][4] = {};
    for (int k0 = 0; k0 < D_; k0 += 16) {
        {
            int arow = tid >> 2, acol = (tid & 3) * 4;
            float4 v = *(const float4*)&A[(size_t)(m0 + arow) * D_ + k0 + acol];
            As[acol + 0][arow] = v.x; As[acol + 1][arow] = v.y;
            As[acol + 2][arow] = v.z; As[acol + 3][arow] = v.w;
        }
        {
            int wrow = tid >> 4, wcol = (tid & 15) * 4;
            *(float4*)&Wa[wrow][wcol] = *(const float4*)&W[(size_t)(k0 + wrow) * D2_ + n0 + wcol];
            *(float4*)&Wg[wrow][wcol] = *(const float4*)&W[(size_t)(k0 + wrow) * D2_ + D_ + n0 + wcol];
        }
        __syncthreads();
#pragma unroll
        for (int kk = 0; kk < 16; kk++) {
            float4 af = *(const float4*)&As[kk][ty * 4];
            float4 ba = *(const float4*)&Wa[kk][tx * 4];
            float4 bg = *(const float4*)&Wg[kk][tx * 4];
            float a4[4] = {af.x, af.y, af.z, af.w};
            float p4[4] = {ba.x, ba.y, ba.z, ba.w};
            float q4[4] = {bg.x, bg.y, bg.z, bg.w};
#pragma unroll
            for (int i = 0; i < 4; i++)
#pragma unroll
                for (int j = 0; j < 4; j++) {
                    cA[i][j] = fmaf(a4[i], p4[j], cA[i][j]);
                    cG[i][j] = fmaf(a4[i], q4[j], cG[i][j]);
                }
        }
        __syncthreads();
    }
#pragma unroll
    for (int i = 0; i < 4; i++) {
        int row = m0 + ty * 4 + i, col = n0 + tx * 4;
        float4 o; float* po = &o.x;
#pragma unroll
        for (int j = 0; j < 4; j++) {
            float a = cA[i][j] + bias[col + j];
            float g = cG[i][j] + bias[D_ + col + j];
            float h = a * (1.f / (1.f + expf(-g)));
            h = h * dw[col + j] + db[col + j];
            h = h * bs[col + j] + bb[col + j];
            h = h * (1.f / (1.f + expf(-h)));
            po[j] = h;
        }
        *(float4*)&outp[(size_t)row * D_ + col] = o;
    }
}

// ---------------- gathered K/V/Ktilde projection for one update row ----------------
__device__ void projKVQ_dev(float* sh,
    float* __restrict__ Ko, float* __restrict__ Vo, float* __restrict__ Qo,
    const float* __restrict__ A, const float* __restrict__ Wk,
    const float* __restrict__ Wv, const float* __restrict__ Wkq,
    int b, int i, int nUpd, int chunk)
{
    float* sa = sh;
    int tid = threadIdx.x;
    if (tid < D_) sa[tid] = A[(size_t)(b * T_ + i * chunk) * D_ + tid];
    __syncthreads();
    if (tid < D_) {
        float sk = 0.f, sv = 0.f, sq = 0.f;
#pragma unroll 8
        for (int kk = 0; kk < D_; kk++) {
            float a = sa[kk];
            sk = fmaf(a, Wk[kk * D_ + tid], sk);
            sv = fmaf(a, Wv[kk * D_ + tid], sv);
            sq = fmaf(a, Wkq[kk * D_ + tid], sq);
        }
        int row = b * nUpd + i;
        Ko[(size_t)row * D_ + tid] = sk;
        Vo[(size_t)row * D_ + tid] = sv;
        Qo[(size_t)row * D_ + tid] = sq;
    }
    __syncthreads();
}

// ---------------- err recurrence for one batch ----------------
template<int N>
__device__ void rec_dev(float* sh, float* __restrict__ ERR,
                        const float* __restrict__ Kmat, const float* __restrict__ Vmat, int b)
{
    float (*sK)[193] = (float (*)[193])sh;
    float* Acf = sh + N * 193;
    float* cd = Acf + N * N;
    int tid = threadIdx.x;
    if (tid < N) cd[tid] = cdv(tid);
    for (int idx = tid; idx < N * D_; idx += 256) {
        int r = idx / D_, c = idx % D_;
        sK[r][c] = Kmat[(size_t)(b * N + r) * D_ + c];
    }
    __syncthreads();
    const int NP = N * (N - 1) / 2;
    for (int p = tid; p < NP; p += 256) {
        int i = (int)((1.0f + sqrtf(1.0f + 8.0f * (float)p)) * 0.5f);
        while (i * (i - 1) / 2 > p) i--;
        while ((i + 1) * i / 2 <= p) i++;
        int j = p - i * (i - 1) / 2;
        float s0 = 0.f, s1 = 0.f;
#pragma unroll 8
        for (int kk = 0; kk < D_; kk += 2) {
            s0 = fmaf(sK[j][kk],     sK[i][kk],     s0);
            s1 = fmaf(sK[j][kk + 1], sK[i][kk + 1], s1);
        }
        Acf[j * N + i] = cd[i - 1 - j] * (s0 + s1);
    }
    __syncthreads();
    if (tid < D_) {
        float err[N];
#pragma unroll
        for (int i = 0; i < N; i++) {
            float a0 = 0.f, a1 = 0.f;
#pragma unroll
            for (int j = 0; j < i; j++) {
                if (j & 1) a1 = fmaf(Acf[j * N + i], err[j], a1);
                else       a0 = fmaf(Acf[j * N + i], err[j], a0);
            }
            err[i] = Vmat[(size_t)(b * N + i) * D_ + tid] - a0 - a1;
            ERR[(size_t)(b * N + i) * D_ + tid] = err[i];
        }
    }
    __syncthreads();
}

// ---------------- delta retrieval + x1, 16 rows per block ----------------
__device__ void qkx1_dev(float* sh, float* __restrict__ x1, const float* __restrict__ xp,
                         const float* __restrict__ Ktil, const float* __restrict__ Ed, int blk)
{
    float* sK = sh;                 // [4*192]
    float* sE = sh + 768;
    float* red = sh + 1536;         // [4][6]
    float* alpha = red + 24;
    int tid = threadIdx.x;
    int b = blk >> 4;
    bool act = tid < D_;
    for (int idx = tid; idx < ND_ * D_; idx += 256) {
        sK[idx] = Ktil[(size_t)b * ND_ * D_ + idx];
        sE[idx] = Ed[(size_t)b * ND_ * D_ + idx];
    }
    __syncthreads();
    int base = blk * 16;
    for (int rr = 0; rr < 16; rr++) {
        int row = base + rr, t = row & (T_ - 1), r = t >> 6;
        float q = 0.f;
        if (act) {
            q = xp[(size_t)row * D_ + tid];
            float p0 = q * sK[tid], p1 = q * sK[192 + tid], p2 = q * sK[384 + tid], p3 = q * sK[576 + tid];
#pragma unroll
            for (int o = 16; o > 0; o >>= 1) {
                p0 += __shfl_xor_sync(~0u, p0, o); p1 += __shfl_xor_sync(~0u, p1, o);
                p2 += __shfl_xor_sync(~0u, p2, o); p3 += __shfl_xor_sync(~0u, p3, o);
            }
            if ((tid & 31) == 0) {
                int w = tid >> 5;
                red[w] = p0; red[6 + w] = p1; red[12 + w] = p2; red[18 + w] = p3;
            }
        }
        __syncthreads();
        if (tid < ND_) {
            float s = 0.f;
#pragma unroll
            for (int w = 0; w < 6; w++) s += red[tid * 6 + w];
            alpha[tid] = (tid <= r) ? cdv(r - tid) * s : 0.f;
        }
        __syncthreads();
        if (act) {
            float s = alpha[0] * sE[tid] + alpha[1] * sE[192 + tid]
                    + alpha[2] * sE[384 + tid] + alpha[3] * sE[576 + tid];
            x1[(size_t)row * D_ + tid] = q + 0.5f * s;
        }
        __syncthreads();
    }
}

// ---------------- LayerNorm, 16 rows per block ----------------
__device__ void ln_dev(float* sh, float* __restrict__ outp, const float* __restrict__ in,
                       const float* __restrict__ g, const float* __restrict__ bb, int blk)
{
    float* red = sh;   // [2][6]
    int tid = threadIdx.x;
    bool act = tid < D_;
    for (int rr = 0; rr < 16; rr++) {
        int row = blk * 16 + rr;
        float v = 0.f;
        if (act) {
            v = in[(size_t)row * D_ + tid];
            float s = v, s2 = v * v;
#pragma unroll
            for (int o = 16; o > 0; o >>= 1) {
                s += __shfl_xor_sync(~0u, s, o);
                s2 += __shfl_xor_sync(~0u, s2, o);
            }
            if ((tid & 31) == 0) { red[tid >> 5] = s; red[6 + (tid >> 5)] = s2; }
        }
        __syncthreads();
        if (act) {
            float ts = 0.f, ts2 = 0.f;
#pragma unroll
            for (int i = 0; i < 6; i++) { ts += red[i]; ts2 += red[6 + i]; }
            float m = ts / D_;
            float var = ts2 / D_ - m * m;
            outp[(size_t)row * D_ + tid] = (v - m) * rsqrtf(var + EPS_) * g[tid] + bb[tid];
        }
        __syncthreads();
    }
}

// ---------------- theta retrieval + x4 + LN2 -> y, 16 t's per block ----------------
__device__ void qkfinal_dev(float* sh, float* __restrict__ y, const float* __restrict__ x3,
                            const float* __restrict__ Ktil, const float* __restrict__ Et,
                            const float* __restrict__ g2, const float* __restrict__ b2, int blk)
{
    float (*sKT)[33] = (float (*)[33])sh;     // [192][33]
    float* red = sh + 192 * 33;               // [32][6]
    float* alpha = red + 192;
    float* cd = alpha + 32;
    float* lred = cd + 32;                    // [2][6]
    int tid = threadIdx.x;
    int b = blk >> 4, tc = blk & 15, t0 = tc * 16;
    if (tid < NT_) cd[tid] = cdv(tid);
    for (int idx = tid; idx < NT_ * D_; idx += 256) {
        int j = idx / D_, e = idx % D_;
        sKT[e][j] = Ktil[(size_t)(b * NT_ + j) * D_ + e];
    }
    __syncthreads();
    bool act = tid < D_;
    int j = tid & 31, g = tid >> 5;
    for (int tt = 0; tt < 16; tt++) {
        int t = t0 + tt, row = b * T_ + t, r = t >> 3;
        if (act) {
            const float* qr = x3 + (size_t)row * D_;
            float part = 0.f;
#pragma unroll
            for (int u = 0; u < 32; u++) part = fmaf(qr[g * 32 + u], sKT[g * 32 + u][j], part);
            red[j * 6 + g] = part;
        }
        __syncthreads();
        if (tid < NT_) {
            float s = 0.f;
#pragma unroll
            for (int gg = 0; gg < 6; gg++) s += red[tid * 6 + gg];
            alpha[tid] = (tid <= r) ? cd[r - tid] * s : 0.f;
        }
        __syncthreads();
        float x4 = 0.f;
        if (act) {
            float s = 0.f;
            for (int jj = 0; jj <= r; jj++)
                s = fmaf(alpha[jj], Et[(size_t)(b * NT_ + jj) * D_ + tid], s);
            x4 = x3[(size_t)row * D_ + tid] + 0.5f * s;
            float sm = x4, s2 = x4 * x4;
#pragma unroll
            for (int o = 16; o > 0; o >>= 1) {
                sm += __shfl_xor_sync(~0u, sm, o);
                s2 += __shfl_xor_sync(~0u, s2, o);
            }
            if ((tid & 31) == 0) { lred[tid >> 5] = sm; lred[6 + (tid >> 5)] = s2; }
        }
        __syncthreads();
        if (act) {
            float ts = 0.f, ts2 = 0.f;
#pragma unroll
            for (int i = 0; i < 6; i++) { ts += lred[i]; ts2 += lred[6 + i]; }
            float m = ts / D_;
            float var = ts2 / D_ - m * m;
            y[(size_t)row * D_ + tid] = (x4 - m) * rsqrtf(var + EPS_) * g2[tid] + b2[tid];
        }
        __syncthreads();
    }
}

// ---------------- pool + classifier for one batch ----------------
__device__ void poolout_dev(float* sh, float* __restrict__ out, const float* __restrict__ y,
                            const float* __restrict__ Wc, const float* __restrict__ bc, int b)
{
    float* pooled = sh;
    int tid = threadIdx.x;
    if (tid < D_) {
        float s = 0.f;
#pragma unroll 4
        for (int t = 0; t < T_; t++) s += y[(size_t)(b * T_ + t) * D_ + tid];
        pooled[tid] = s * (1.f / T_);
    }
    __syncthreads();
    if (tid < NC_) {
        float acc = bc[tid];
#pragma unroll 8
        for (int e = 0; e < D_; e++) acc = fmaf(pooled[e], Wc[e * NC_ + tid], acc);
        out[b * NC_ + tid] = acc;
    }
}

// =====================================================================
__global__ void __launch_bounds__(256) mega_kernel(
    const float* __restrict__ x, const float* __restrict__ W_in, const float* __restrict__ b_in,
    const float* __restrict__ Wv_a, const float* __restrict__ bv_a,
    const float* __restrict__ Wo_a, const float* __restrict__ bo_a,
    const float* __restrict__ ln1_g, const float* __restrict__ ln1_b,
    const float* __restrict__ pw1_w, const float* __restrict__ pw1_b,
    const float* __restrict__ dw_w, const float* __restrict__ dw_b,
    const float* __restrict__ bn_s, const float* __restrict__ bn_b,
    const float* __restrict__ pw2_w, const float* __restrict__ pw2_b,
    const float* __restrict__ Wk_t, const float* __restrict__ Wv_t, const float* __restrict__ Wq_t,
    const float* __restrict__ Wk_d, const float* __restrict__ Wv_d, const float* __restrict__ Wq_d,
    const float* __restrict__ ln2_g, const float* __restrict__ ln2_b,
    const float* __restrict__ Wc, const float* __restrict__ bc,
    float* __restrict__ out)
{
    __shared__ __align__(16) float sh[SH_SZ];
    int blk = blockIdx.x, tid = threadIdx.x;

    // ---- S0: xp GEMM (96 tiles) + weight folds (27 tiles + bao) ----
    if (blk < 96) {
        int mt = blk / 3, nt = blk % 3;
        dev_gemm_tile(sh, x, MEL_, W_in, D_, false, b_in, nullptr, g_xp, D_, mt * 64, nt * 64, MEL_);
    } else if (blk < 105) {
        int p = blk - 96;
        dev_gemm_tile(sh, Wv_a, D_, Wo_a, D_, false, nullptr, nullptr, g_Wao, D_, (p / 3) * 64, (p % 3) * 64, D_);
    } else if (blk < 114) {
        int p = blk - 105;
        dev_gemm_tile(sh, Wk_d, D_, Wq_d, D_, true, nullptr, nullptr, g_Wkqd, D_, (p / 3) * 64, (p % 3) * 64, D_);
    } else if (blk < 123) {
        int p = blk - 114;
        dev_gemm_tile(sh, Wk_t, D_, Wq_t, D_, true, nullptr, nullptr, g_Wkqt, D_, (p / 3) * 64, (p % 3) * 64, D_);
    } else if (blk == 123) {
        if (tid < D_) {
            float s = bo_a[tid];
#pragma unroll 8
            for (int e = 0; e < D_; e++) s = fmaf(bv_a[e], Wo_a[e * D_ + tid], s);
            g_bao[tid] = s;
        }
    }
    gbar();

    // ---- S1: delta K/V/Ktilde ----
    if (blk < B_ * ND_) projKVQ_dev(sh, g_Kd, g_Vd, g_Qd, g_xp, Wk_d, Wv_d, g_Wkqd,
                                    blk / ND_, blk % ND_, ND_, 64);
    gbar();

    // ---- S2: delta err recurrence ----
    if (blk < B_) rec_dev<ND_>(sh, g_Ed, g_Kd, g_Vd, blk);
    gbar();

    // ---- S3: x1 = xp + 0.5 * delta retrieval ----
    qkx1_dev(sh, g_x1, g_xp, g_Qd, g_Ed, blk);
    gbar();

    // ---- S4: x2 = x1 + x1@Wao + bao ----
    if (blk < 96) {
        int mt = blk / 3, nt = blk % 3;
        dev_gemm_tile(sh, g_x1, D_, g_Wao, D_, false, g_bao, g_x1, g_x2, D_, mt * 64, nt * 64, D_);
    }
    gbar();

    // ---- S5: h = LN1(x2) ----
    ln_dev(sh, g_h, g_x2, ln1_g, ln1_b, blk);
    gbar();

    // ---- S6: g2 = SiLU(BN(dw(GLU(h@pw1+b)))) ----
    if (blk < 96) {
        int mt = blk / 3, nt = blk % 3;
        dev_glu_tile(sh, g_h, pw1_w, pw1_b, dw_w, dw_b, bn_s, bn_b, g_g2, mt * 64, nt * 64);
    }
    gbar();

    // ---- S7: x3 = x2 + g2@pw2 + b ----
    if (blk < 96) {
        int mt = blk / 3, nt = blk % 3;
        dev_gemm_tile(sh, g_g2, D_, pw2_w, D_, false, pw2_b, g_x2, g_x3, D_, mt * 64, nt * 64, D_);
    }
    gbar();

    // ---- S8: theta K/V/Ktilde (256 items, 2 per block) ----
    for (int it = blk; it < B_ * NT_; it += G_)
        projKVQ_dev(sh, g_Kt, g_Vt, g_Qt, g_x3, Wk_t, Wv_t, g_Wkqt, it / NT_, it % NT_, NT_, 8);
    gbar();

    // ---- S9: theta err recurrence ----
    if (blk < B_) rec_dev<NT_>(sh, g_Et, g_Kt, g_Vt, blk);
    gbar();

    // ---- S10: y = LN2(x3 + 0.5 * theta retrieval) ----
    qkfinal_dev(sh, g_y, g_x3, g_Qt, g_Et, ln2_g, ln2_b, blk);
    gbar();

    // ---- S11: pool + classifier ----
    if (blk < B_) poolout_dev(sh, out, g_y, Wc, bc, blk);
}

// =====================================================================
extern "C" void kernel_launch(void* const* d_in, const int* in_sizes, int n_in,
                              void* d_out, int out_size)
{
    const float* x     = (const float*)d_in[0];
    const float* W_in  = (const float*)d_in[1];
    const float* b_in  = (const float*)d_in[2];
    const float* Wv_a  = (const float*)d_in[3];
    const float* bv_a  = (const float*)d_in[4];
    const float* Wo_a  = (const float*)d_in[5];
    const float* bo_a  = (const float*)d_in[6];
    const float* ln1_g = (const float*)d_in[7];
    const float* ln1_b = (const float*)d_in[8];
    const float* pw1_w = (const float*)d_in[9];
    const float* pw1_b = (const float*)d_in[10];
    const float* dw_w  = (const float*)d_in[11];
    const float* dw_b  = (const float*)d_in[12];
    const float* bn_s  = (const float*)d_in[13];
    const float* bn_b  = (const float*)d_in[14];
    const float* pw2_w = (const float*)d_in[15];
    const float* pw2_b = (const float*)d_in[16];
    const float* Wk_t  = (const float*)d_in[17];
    const float* Wv_t  = (const float*)d_in[18];
    const float* Wq_t  = (const float*)d_in[19];
    const float* Wk_d  = (const float*)d_in[20];
    const float* Wv_d  = (const float*)d_in[21];
    const float* Wq_d  = (const float*)d_in[22];
    const float* ln2_g = (const float*)d_in[23];
    const float* ln2_b = (const float*)d_in[24];
    const float* Wc    = (const float*)d_in[25];
    const float* bc    = (const float*)d_in[26];
    float* out = (float*)d_out;

    mega_kernel<<<G_, 256>>>(x, W_in, b_in, Wv_a, bv_a, Wo_a, bo_a,
                             ln1_g, ln1_b, pw1_w, pw1_b, dw_w, dw_b, bn_s, bn_b,
                             pw2_w, pw2_b, Wk_t, Wv_t, Wq_t, Wk_d, Wv_d, Wq_d,
                             ln2_g, ln2_b, Wc, bc, out);
}

// round 6
// speedup vs baseline: 1.1204x; 1.1204x over previous
#include <cuda_runtime.h>
#include <math.h>

#define B_   8
#define T_   256
#define MEL_ 128
#define D_   192
#define NC_  20
#define D2_  384
#define NT_  32
#define ND_  4
#define EPS_ 1e-5f

__device__ float g_xp [B_*T_*D_];
__device__ float g_x2 [B_*T_*D_];
__device__ float g_g2 [B_*T_*D_];
__device__ float g_x3 [B_*T_*D_];
__device__ float g_Kd [B_*ND_*D_];
__device__ float g_Vd [B_*ND_*D_];
__device__ float g_Qd [B_*ND_*D_];
__device__ float g_Ed [B_*ND_*D_];
__device__ float g_Fd [B_*ND_*D_];
__device__ float g_Kt [B_*NT_*D_];
__device__ float g_Vt [B_*NT_*D_];
__device__ float g_Qt [B_*NT_*D_];
__device__ float g_Et [B_*NT_*D_];
__device__ float g_Wao [D_*D_];
__device__ float g_bao [D_];
__device__ float g_Wkqd[D_*D_];
__device__ float g_Wkqt[D_*D_];
__device__ float g_pp [B_*16*D_];

__device__ __forceinline__ float cdv(int d) {
    const float L2A = -0.014499569695115089f;
    const float L2E = -0.152003093445049970f;
    float n = (float)(d + 1);
    return (exp2f(n * L2A) - exp2f(n * L2E)) * (0.1f / 0.09f);
}

__device__ __forceinline__ void dev_gemm_tile(float* sh,
    const float* __restrict__ A, int ldA, const float* __restrict__ W, int ldW, bool transB,
    const float* __restrict__ bias, const float* __restrict__ res, float* __restrict__ C, int ldC,
    int m0, int n0, int K)
{
    float (*As)[68] = (float (*)[68])sh;
    float (*Ws)[64] = (float (*)[64])(sh + 16 * 68);
    int tid = threadIdx.x;
    int tx = tid & 15, ty = tid >> 4;
    float c[4][4] = {};
    for (int k0 = 0; k0 < K; k0 += 16) {
        {
            int arow = tid >> 2, acol = (tid & 3) * 4;
            float4 v = *(const float4*)&A[(size_t)(m0 + arow) * ldA + k0 + acol];
            As[acol + 0][arow] = v.x; As[acol + 1][arow] = v.y;
            As[acol + 2][arow] = v.z; As[acol + 3][arow] = v.w;
        }
        {
            int wrow = tid >> 4, wcol = (tid & 15) * 4;
            if (transB) {
#pragma unroll
                for (int u = 0; u < 4; u++)
                    Ws[wrow][wcol + u] = W[(size_t)(n0 + wcol + u) * ldW + k0 + wrow];
            } else {
                *(float4*)&Ws[wrow][wcol] = *(const float4*)&W[(size_t)(k0 + wrow) * ldW + n0 + wcol];
            }
        }
        __syncthreads();
#pragma unroll
        for (int kk = 0; kk < 16; kk++) {
            float4 af = *(const float4*)&As[kk][ty * 4];
            float4 bf = *(const float4*)&Ws[kk][tx * 4];
            float a4[4] = {af.x, af.y, af.z, af.w};
            float b4[4] = {bf.x, bf.y, bf.z, bf.w};
#pragma unroll
            for (int i = 0; i < 4; i++)
#pragma unroll
                for (int j = 0; j < 4; j++) c[i][j] = fmaf(a4[i], b4[j], c[i][j]);
        }
        __syncthreads();
    }
#pragma unroll
    for (int i = 0; i < 4; i++) {
        int row = m0 + ty * 4 + i, col = n0 + tx * 4;
        float4 o; float* po = &o.x;
#pragma unroll
        for (int j = 0; j < 4; j++) {
            float v = c[i][j];
            if (bias) v += bias[col + j];
            if (res)  v += res[(size_t)row * ldC + col + j];
            po[j] = v;
        }
        *(float4*)&C[(size_t)row * ldC + col] = o;
    }
}

__global__ void __launch_bounds__(256) k0_comb(
    const float* __restrict__ x, const float* __restrict__ W_in, const float* __restrict__ b_in,
    const float* __restrict__ Wv_a, const float* __restrict__ Wo_a,
    const float* __restrict__ bv_a, const float* __restrict__ bo_a,
    const float* __restrict__ Wk_d, const float* __restrict__ Wq_d,
    const float* __restrict__ Wk_t, const float* __restrict__ Wq_t)
{
    __shared__ __align__(16) float sh[16 * 68 + 16 * 64];
    int blk = blockIdx.x, tid = threadIdx.x;
    if (blk < 96) {
        dev_gemm_tile(sh, x, MEL_, W_in, D_, false, b_in, nullptr, g_xp, D_,
                      (blk / 3) * 64, (blk % 3) * 64, MEL_);
    } else if (blk < 105) {
        int p = blk - 96;
        dev_gemm_tile(sh, Wv_a, D_, Wo_a, D_, false, nullptr, nullptr, g_Wao, D_,
                      (p / 3) * 64, (p % 3) * 64, D_);
    } else if (blk < 114) {
        int p = blk - 105;
        dev_gemm_tile(sh, Wk_d, D_, Wq_d, D_, true, nullptr, nullptr, g_Wkqd, D_,
                      (p / 3) * 64, (p % 3) * 64, D_);
    } else if (blk < 123) {
        int p = blk - 114;
        dev_gemm_tile(sh, Wk_t, D_, Wq_t, D_, true, nullptr, nullptr, g_Wkqt, D_,
                      (p / 3) * 64, (p % 3) * 64, D_);
    } else {
        if (tid < D_) {
            float s = bo_a[tid];
#pragma unroll 8
            for (int e = 0; e < D_; e++) s = fmaf(bv_a[e], Wo_a[e * D_ + tid], s);
            g_bao[tid] = s;
        }
    }
}

__global__ void __launch_bounds__(192) projKVQ(
    float* __restrict__ Ko, float* __restrict__ Vo, float* __restrict__ Qo,
    const float* __restrict__ A, const float* __restrict__ Wk,
    const float* __restrict__ Wv, const float* __restrict__ Wkq, int nUpd, int chunk)
{
    __shared__ float sa[D_];
    int blk = blockIdx.x;
    int b = blk / nUpd, i = blk % nUpd;
    int tid = threadIdx.x;
    sa[tid] = A[(size_t)(b * T_ + i * chunk) * D_ + tid];
    __syncthreads();
    if (tid < 144) {
        int gsel = tid / 48, q = tid % 48;
        const float* W = (gsel == 0) ? Wk : (gsel == 1) ? Wv : Wkq;
        float ax = 0.f, ay = 0.f, az = 0.f, aw = 0.f;
#pragma unroll 4
        for (int kk = 0; kk < D_; kk++) {
            float a = sa[kk];
            float4 w = *(const float4*)&W[kk * D_ + 4 * q];
            ax = fmaf(a, w.x, ax); ay = fmaf(a, w.y, ay);
            az = fmaf(a, w.z, az); aw = fmaf(a, w.w, aw);
        }
        float* O = (gsel == 0) ? Ko : (gsel == 1) ? Vo : Qo;
        float4 o = {ax, ay, az, aw};
        *(float4*)&O[(size_t)blk * D_ + 4 * q] = o;
    }
}

__global__ void __launch_bounds__(256) rec_d_kernel(
    float* __restrict__ ERR, float* __restrict__ F,
    const float* __restrict__ Kmat, const float* __restrict__ Vmat,
    const float* __restrict__ Wao)
{
    __shared__ float sK[ND_][D_ + 1];
    __shared__ float sE[ND_][D_];
    __shared__ float Acf[ND_][ND_];
    int b = blockIdx.x, tid = threadIdx.x;
    for (int idx = tid; idx < ND_ * D_; idx += 256)
        sK[idx / D_][idx % D_] = Kmat[(size_t)b * ND_ * D_ + idx];
    __syncthreads();
    if (tid < 6) {
        const int pi[6] = {1, 2, 2, 3, 3, 3};
        const int pj[6] = {0, 0, 1, 0, 1, 2};
        int i = pi[tid], j = pj[tid];
        float s0 = 0.f, s1 = 0.f;
#pragma unroll 8
        for (int kk = 0; kk < D_; kk += 2) {
            s0 = fmaf(sK[j][kk],     sK[i][kk],     s0);
            s1 = fmaf(sK[j][kk + 1], sK[i][kk + 1], s1);
        }
        Acf[j][i] = cdv(i - 1 - j) * (s0 + s1);
    }
    __syncthreads();
    if (tid < D_) {
        float err[ND_];
#pragma unroll
        for (int i = 0; i < ND_; i++) {
            float s = Vmat[(size_t)(b * ND_ + i) * D_ + tid];
#pragma unroll
            for (int j = 0; j < i; j++) s -= Acf[j][i] * err[j];
            err[i] = s;
            sE[i][tid] = s;
            ERR[(size_t)(b * ND_ + i) * D_ + tid] = s;
        }
    }
    __syncthreads();
    {
        int j = tid / 48, q = tid % 48;
        if (tid < 192) {
            float4 acc = *(float4*)&sE[j][4 * q];
#pragma unroll 4
            for (int e = 0; e < D_; e++) {
                float a = sE[j][e];
                float4 w = *(const float4*)&Wao[e * D_ + 4 * q];
                acc.x = fmaf(a, w.x, acc.x); acc.y = fmaf(a, w.y, acc.y);
                acc.z = fmaf(a, w.z, acc.z); acc.w = fmaf(a, w.w, acc.w);
            }
            *(float4*)&F[(size_t)(b * ND_ + j) * D_ + 4 * q] = acc;
        }
    }
}

__global__ void __launch_bounds__(256) x2_fused(
    const float* __restrict__ xp, const float* __restrict__ Wao, const float* __restrict__ bao,
    const float* __restrict__ Qd, const float* __restrict__ Fd, float* __restrict__ x2)
{
    __shared__ __align__(16) float As[16][68];
    __shared__ __align__(16) float Ws[16][64];
    __shared__ __align__(16) float sQ[ND_ * D_];
    __shared__ __align__(16) float sF[ND_ * D_];
    __shared__ float alph[64][4];
    int blk = blockIdx.x;
    int m0 = (blk / 3) * 64, n0 = (blk % 3) * 64;
    int b = m0 >> 8;
    int tid = threadIdx.x, tx = tid & 15, ty = tid >> 4;
    for (int idx = tid; idx < ND_ * D_; idx += 256) {
        sQ[idx] = Qd[(size_t)b * ND_ * D_ + idx];
        sF[idx] = Fd[(size_t)b * ND_ * D_ + idx];
    }
    float c[4][4] = {};
    for (int k0 = 0; k0 < D_; k0 += 16) {
        {
            int arow = tid >> 2, acol = (tid & 3) * 4;
            float4 v = *(const float4*)&xp[(size_t)(m0 + arow) * D_ + k0 + acol];
            As[acol + 0][arow] = v.x; As[acol + 1][arow] = v.y;
            As[acol + 2][arow] = v.z; As[acol + 3][arow] = v.w;
        }
        {
            int wrow = tid >> 4, wcol = (tid & 15) * 4;
            *(float4*)&Ws[wrow][wcol] = *(const float4*)&Wao[(size_t)(k0 + wrow) * D_ + n0 + wcol];
        }
        __syncthreads();
#pragma unroll
        for (int kk = 0; kk < 16; kk++) {
            float4 af = *(const float4*)&As[kk][ty * 4];
            float4 bf = *(const float4*)&Ws[kk][tx * 4];
            float a4[4] = {af.x, af.y, af.z, af.w};
            float b4[4] = {bf.x, bf.y, bf.z, bf.w};
#pragma unroll
            for (int i = 0; i < 4; i++)
#pragma unroll
                for (int j = 0; j < 4; j++) c[i][j] = fmaf(a4[i], b4[j], c[i][j]);
        }
        __syncthreads();
    }
    {
        int row = tid >> 2, j = tid & 3;
        const float4* xr = (const float4*)&xp[(size_t)(m0 + row) * D_];
        const float4* qj = (const float4*)&sQ[j * D_];
        float s = 0.f;
#pragma unroll 8
        for (int i4 = 0; i4 < 48; i4++) {
            float4 a = xr[i4], q = qj[i4];
            s = fmaf(a.x, q.x, s); s = fmaf(a.y, q.y, s);
            s = fmaf(a.z, q.z, s); s = fmaf(a.w, q.w, s);
        }
        int t = (m0 + row) & (T_ - 1), r = t >> 6;
        alph[row][j] = (j <= r) ? 0.5f * cdv(r - j) * s : 0.f;
    }
    __syncthreads();
#pragma unroll
    for (int i = 0; i < 4; i++) {
        int lrow = ty * 4 + i, row = m0 + lrow, col = n0 + tx * 4;
        float4 o; float* po = &o.x;
#pragma unroll
        for (int j = 0; j < 4; j++) {
            float v = c[i][j] + bao[col + j] + xp[(size_t)row * D_ + col + j];
#pragma unroll
            for (int jj = 0; jj < ND_; jj++)
                v = fmaf(alph[lrow][jj], sF[jj * D_ + col + j], v);
            po[j] = v;
        }
        *(float4*)&x2[(size_t)row * D_ + col] = o;
    }
}

__global__ void __launch_bounds__(256) glu_ln(
    const float* __restrict__ x2, const float* __restrict__ g1, const float* __restrict__ b1,
    const float* __restrict__ W, const float* __restrict__ bias,
    const float* __restrict__ dw, const float* __restrict__ db,
    const float* __restrict__ bs, const float* __restrict__ bb, float* __restrict__ outp)
{
    extern __shared__ __align__(16) float sh[];
    float (*Xs)[68] = (float (*)[68])sh;
    float* Wa = sh + 192 * 68;
    float* Wg = Wa + 16 * 64;
    float* rowm = Wg + 16 * 64;
    float* rowr = rowm + 64;
    int blk = blockIdx.x;
    int m0 = (blk / 3) * 64, n0 = (blk % 3) * 64;
    int tid = threadIdx.x, tx = tid & 15, ty = tid >> 4;
    for (int k0 = 0; k0 < D_; k0 += 16) {
        int arow = tid >> 2, acol = (tid & 3) * 4;
        float4 v = *(const float4*)&x2[(size_t)(m0 + arow) * D_ + k0 + acol];
        Xs[k0 + acol + 0][arow] = v.x; Xs[k0 + acol + 1][arow] = v.y;
        Xs[k0 + acol + 2][arow] = v.z; Xs[k0 + acol + 3][arow] = v.w;
    }
    __syncthreads();
    if (tid < 64) {
        float s = 0.f, s2 = 0.f;
#pragma unroll 8
        for (int k = 0; k < D_; k++) { float v = Xs[k][tid]; s += v; s2 += v * v; }
        float m = s / D_;
        rowm[tid] = m;
        rowr[tid] = rsqrtf(s2 / D_ - m * m + EPS_);
    }
    __syncthreads();
    for (int idx = tid; idx < D_ * 64; idx += 256) {
        int k = idx >> 6, r = idx & 63;
        Xs[k][r] = (Xs[k][r] - rowm[r]) * rowr[r] * g1[k] + b1[k];
    }
    __syncthreads();
    float cA[4][4] = {}, cG[4][4] = {};
    for (int k0 = 0; k0 < D_; k0 += 16) {
        {
            int wrow = tid >> 4, wcol = (tid & 15) * 4;
            *(float4*)&Wa[wrow * 64 + wcol] = *(const float4*)&W[(size_t)(k0 + wrow) * D2_ + n0 + wcol];
            *(float4*)&Wg[wrow * 64 + wcol] = *(const float4*)&W[(size_t)(k0 + wrow) * D2_ + D_ + n0 + wcol];
        }
        __syncthreads();
#pragma unroll
        for (int kk = 0; kk < 16; kk++) {
            float4 af = *(const float4*)&Xs[k0 + kk][ty * 4];
            float4 ba = *(const float4*)&Wa[kk * 64 + tx * 4];
            float4 bg = *(const float4*)&Wg[kk * 64 + tx * 4];
            float a4[4] = {af.x, af.y, af.z, af.w};
            float p4[4] = {ba.x, ba.y, ba.z, ba.w};
            float q4[4] = {bg.x, bg.y, bg.z, bg.w};
#pragma unroll
            for (int i = 0; i < 4; i++)
#pragma unroll
                for (int j = 0; j < 4; j++) {
                    cA[i][j] = fmaf(a4[i], p4[j], cA[i][j]);
                    cG[i][j] = fmaf(a4[i], q4[j], cG[i][j]);
                }
        }
        __syncthreads();
    }
#pragma unroll
    for (int i = 0; i < 4; i++) {
        int row = m0 + ty * 4 + i, col = n0 + tx * 4;
        float4 o; float* po = &o.x;
#pragma unroll
        for (int j = 0; j < 4; j++) {
            float a = cA[i][j] + bias[col + j];
            float g = cG[i][j] + bias[D_ + col + j];
            float h = a * (1.f / (1.f + expf(-g)));
            h = h * dw[col + j] + db[col + j];
            h = h * bs[col + j] + bb[col + j];
            h = h * (1.f / (1.f + expf(-h)));
            po[j] = h;
        }
        *(float4*)&outp[(size_t)row * D_ + col] = o;
    }
}

__global__ void __launch_bounds__(256) gemm_pw2(
    const float* __restrict__ A, const float* __restrict__ W,
    const float* __restrict__ bias, const float* __restrict__ res, float* __restrict__ C)
{
    __shared__ __align__(16) float sh[16 * 68 + 16 * 64];
    dev_gemm_tile(sh, A, D_, W, D_, false, bias, res, C, D_,
                  (blockIdx.x / 3) * 64, (blockIdx.x % 3) * 64, D_);
}

__global__ void __launch_bounds__(256) rec_t_kernel(
    float* __restrict__ ERR, const float* __restrict__ Kmat, const float* __restrict__ Vmat)
{
    __shared__ float sK[NT_][D_ + 1];
    __shared__ float Acf[NT_][NT_];
    __shared__ float cd[NT_];
    int b = blockIdx.x, tid = threadIdx.x;
    if (tid < NT_) cd[tid] = cdv(tid);
    for (int idx = tid; idx < NT_ * D_; idx += 256)
        sK[idx / D_][idx % D_] = Kmat[(size_t)b * NT_ * D_ + idx];
    __syncthreads();
    const int NP = NT_ * (NT_ - 1) / 2;
    for (int p = tid; p < NP; p += 256) {
        int i = (int)((1.0f + sqrtf(1.0f + 8.0f * (float)p)) * 0.5f);
        while (i * (i - 1) / 2 > p) i--;
        while ((i + 1) * i / 2 <= p) i++;
        int j = p - i * (i - 1) / 2;
        float s0 = 0.f, s1 = 0.f;
#pragma unroll 8
        for (int kk = 0; kk < D_; kk += 2) {
            s0 = fmaf(sK[j][kk],     sK[i][kk],     s0);
            s1 = fmaf(sK[j][kk + 1], sK[i][kk + 1], s1);
        }
        Acf[j][i] = cd[i - 1 - j] * (s0 + s1);
    }
    __syncthreads();
    if (tid < D_) {
        float err[NT_];
#pragma unroll
        for (int i = 0; i < NT_; i++) {
            float a0 = 0.f, a1 = 0.f;
#pragma unroll
            for (int j = 0; j < i; j++) {
                if (j & 1) a1 = fmaf(Acf[j][i], err[j], a1);
                else       a0 = fmaf(Acf[j][i], err[j], a0);
            }
            err[i] = Vmat[(size_t)(b * NT_ + i) * D_ + tid] - a0 - a1;
            ERR[(size_t)(b * NT_ + i) * D_ + tid] = err[i];
        }
    }
}

__global__ void __launch_bounds__(192) qkfinal(
    const float* __restrict__ x3, const float* __restrict__ Kt, const float* __restrict__ Et,
    const float* __restrict__ g2, const float* __restrict__ b2, float* __restrict__ pp)
{
    extern __shared__ __align__(16) float sh[];
    float (*sKT)[33] = (float (*)[33])sh;
    float* sEt = sh + 192 * 33;
    float* red = sEt + NT_ * D_;
    float* alpha = red + 192;
    float* cd = alpha + 32;
    float* lred = cd + 32;
    int blk = blockIdx.x;
    int b = blk >> 4, tc = blk & 15, t0 = tc * 16;
    int tid = threadIdx.x;
    if (tid < NT_) cd[tid] = cdv(tid);
    for (int idx = tid; idx < NT_ * D_; idx += 192) {
        int j = idx / D_, e = idx % D_;
        sKT[e][j] = Kt[(size_t)(b * NT_ + j) * D_ + e];
        sEt[idx] = Et[(size_t)b * NT_ * D_ + idx];
    }
    __syncthreads();
    int j = tid & 31, g = tid >> 5;
    float ps = 0.f;
    for (int tt = 0; tt < 16; tt++) {
        int t = t0 + tt, row = b * T_ + t, r = t >> 3;
        {
            const float* qr = x3 + (size_t)row * D_;
            float part = 0.f;
#pragma unroll
            for (int u = 0; u < 32; u++) part = fmaf(qr[g * 32 + u], sKT[g * 32 + u][j], part);
            red[j * 6 + g] = part;
        }
        __syncthreads();
        if (tid < NT_) {
            float s = 0.f;
#pragma unroll
            for (int gg = 0; gg < 6; gg++) s += red[tid * 6 + gg];
            alpha[tid] = (tid <= r) ? cd[r - tid] * s : 0.f;
        }
        __syncthreads();
        float s = 0.f;
        for (int jj = 0; jj <= r; jj++) s = fmaf(alpha[jj], sEt[jj * D_ + tid], s);
        float x4 = x3[(size_t)row * D_ + tid] + 0.5f * s;
        float sm = x4, s2 = x4 * x4;
#pragma unroll
        for (int o = 16; o > 0; o >>= 1) {
            sm += __shfl_xor_sync(~0u, sm, o);
            s2 += __shfl_xor_sync(~0u, s2, o);
        }
        if ((tid & 31) == 0) { lred[tid >> 5] = sm; lred[6 + (tid >> 5)] = s2; }
        __syncthreads();
        float ts = 0.f, ts2 = 0.f;
#pragma unroll
        for (int i = 0; i < 6; i++) { ts += lred[i]; ts2 += lred[6 + i]; }
        float m = ts / D_;
        float var = ts2 / D_ - m * m;
        ps += (x4 - m) * rsqrtf(var + EPS_) * g2[tid] + b2[tid];
        __syncthreads();
    }
    pp[(size_t)(b * 16 + tc) * D_ + tid] = ps;
}

__global__ void __launch_bounds__(192) poolcls(
    const float* __restrict__ pp, const float* __restrict__ Wc,
    const float* __restrict__ bc, float* __restrict__ out)
{
    __shared__ float pooled[D_];
    int b = blockIdx.x, tid = threadIdx.x;
    float s = 0.f;
#pragma unroll
    for (int q = 0; q < 16; q++) s += pp[(size_t)(b * 16 + q) * D_ + tid];
    pooled[tid] = s * (1.f / T_);
    __syncthreads();
    if (tid < NC_) {
        float acc = bc[tid];
#pragma unroll 8
        for (int e = 0; e < D_; e++) acc = fmaf(pooled[e], Wc[e * NC_ + tid], acc);
        out[b * NC_ + tid] = acc;
    }
}

extern "C" void kernel_launch(void* const* d_in, const int* in_sizes, int n_in,
                              void* d_out, int out_size)
{
    const float* x     = (const float*)d_in[0];
    const float* W_in  = (const float*)d_in[1];
    const float* b_in  = (const float*)d_in[2];
    const float* Wv_a  = (const float*)d_in[3];
    const float* bv_a  = (const float*)d_in[4];
    const float* Wo_a  = (const float*)d_in[5];
    const float* bo_a  = (const float*)d_in[6];
    const float* ln1_g = (const float*)d_in[7];
    const float* ln1_b = (const float*)d_in[8];
    const float* pw1_w = (const float*)d_in[9];
    const float* pw1_b = (const float*)d_in[10];
    const float* dw_w  = (const float*)d_in[11];
    const float* dw_b  = (const float*)d_in[12];
    const float* bn_s  = (const float*)d_in[13];
    const float* bn_b  = (const float*)d_in[14];
    const float* pw2_w = (const float*)d_in[15];
    const float* pw2_b = (const float*)d_in[16];
    const float* Wk_t  = (const float*)d_in[17];
    const float* Wv_t  = (const float*)d_in[18];
    const float* Wq_t  = (const float*)d_in[19];
    const float* Wk_d  = (const float*)d_in[20];
    const float* Wv_d  = (const float*)d_in[21];
    const float* Wq_d  = (const float*)d_in[22];
    const float* ln2_g = (const float*)d_in[23];
    const float* ln2_b = (const float*)d_in[24];
    const float* Wc    = (const float*)d_in[25];
    const float* bc    = (const float*)d_in[26];
    float* out = (float*)d_out;

    float *xp, *x2, *g2p, *x3, *Kd, *Vd, *Qd, *Ed, *Fd, *Kt, *Vt, *Qt, *Et;
    float *Wao, *bao, *Wkqd, *Wkqt, *pp;
    cudaGetSymbolAddress((void**)&xp,   g_xp);
    cudaGetSymbolAddress((void**)&x2,   g_x2);
    cudaGetSymbolAddress((void**)&g2p,  g_g2);
    cudaGetSymbolAddress((void**)&x3,   g_x3);
    cudaGetSymbolAddress((void**)&Kd,   g_Kd);
    cudaGetSymbolAddress((void**)&Vd,   g_Vd);
    cudaGetSymbolAddress((void**)&Qd,   g_Qd);
    cudaGetSymbolAddress((void**)&Ed,   g_Ed);
    cudaGetSymbolAddress((void**)&Fd,   g_Fd);
    cudaGetSymbolAddress((void**)&Kt,   g_Kt);
    cudaGetSymbolAddress((void**)&Vt,   g_Vt);
    cudaGetSymbolAddress((void**)&Qt,   g_Qt);
    cudaGetSymbolAddress((void**)&Et,   g_Et);
    cudaGetSymbolAddress((void**)&Wao,  g_Wao);
    cudaGetSymbolAddress((void**)&bao,  g_bao);
    cudaGetSymbolAddress((void**)&Wkqd, g_Wkqd);
    cudaGetSymbolAddress((void**)&Wkqt, g_Wkqt);
    cudaGetSymbolAddress((void**)&pp,   g_pp);

    const int GLU_SMEM = (192 * 68 + 2 * 16 * 64 + 128) * 4;
    const int QKF_SMEM = (192 * 33 + NT_ * D_ + 192 + 32 + 32 + 12) * 4;
    cudaFuncSetAttribute(glu_ln,  cudaFuncAttributeMaxDynamicSharedMemorySize, GLU_SMEM);
    cudaFuncSetAttribute(qkfinal, cudaFuncAttributeMaxDynamicSharedMemorySize, QKF_SMEM);

    k0_comb<<<124, 256>>>(x, W_in, b_in, Wv_a, Wo_a, bv_a, bo_a, Wk_d, Wq_d, Wk_t, Wq_t);
    projKVQ<<<B_ * ND_, 192>>>(Kd, Vd, Qd, xp, Wk_d, Wv_d, Wkqd, ND_, 64);
    rec_d_kernel<<<B_, 256>>>(Ed, Fd, Kd, Vd, Wao);
    x2_fused<<<96, 256>>>(xp, Wao, bao, Qd, Fd, x2);
    glu_ln<<<96, 256, GLU_SMEM>>>(x2, ln1_g, ln1_b, pw1_w, pw1_b, dw_w, dw_b, bn_s, bn_b, g2p);
    gemm_pw2<<<96, 256>>>(g2p, pw2_w, pw2_b, x2, x3);
    projKVQ<<<B_ * NT_, 192>>>(Kt, Vt, Qt, x3, Wk_t, Wv_t, Wkqt, NT_, 8);
    rec_t_kernel<<<B_, 256>>>(Et, Kt, Vt);
    qkfinal<<<B_ * 16, 192, QKF_SMEM>>>(x3, Qt, Et, ln2_g, ln2_b, pp);
    poolcls<<<B_, 192>>>(pp, Wc, bc, out);
}

// round 7
// speedup vs baseline: 1.1801x; 1.0533x over previous
#include <cuda_runtime.h>
#include <math.h>

#define B_   8
#define T_   256
#define MEL_ 128
#define D_   192
#define NC_  20
#define D2_  384
#define NT_  32
#define ND_  4
#define EPS_ 1e-5f

__device__ float g_xp [B_*T_*D_];
__device__ float g_x2 [B_*T_*D_];
__device__ float g_g2 [B_*T_*D_];
__device__ float g_x3 [B_*T_*D_];
__device__ float g_Kd [B_*ND_*D_];
__device__ float g_Vd [B_*ND_*D_];
__device__ float g_Qd [B_*ND_*D_];
__device__ float g_Ed [B_*ND_*D_];
__device__ float g_Fd [B_*ND_*D_];
__device__ float g_Kt [B_*NT_*D_];
__device__ float g_Vt [B_*NT_*D_];
__device__ float g_Qt [B_*NT_*D_];
__device__ float g_Et [B_*NT_*D_];
__device__ float g_Wao [D_*D_];
__device__ float g_bao [D_];
__device__ float g_Wkqd[D_*D_];
__device__ float g_Wkqt[D_*D_];
__device__ float g_pp [B_*16*D_];

__device__ __forceinline__ float cdv(int d) {
    const float L2A = -0.014499569695115089f;   // log2(0.99)
    const float L2E = -0.152003093445049970f;   // log2(0.90)
    float n = (float)(d + 1);
    return (exp2f(n * L2A) - exp2f(n * L2E)) * (0.1f / 0.09f);
}

// ---------------- full-K smem-resident GEMM pieces (256 threads, 64x64 tile) ----------------
// As layout: Asf[k*68 + row]  (transposed, padded stride 68)
// Ws layout: Wsf[k*64 + col]
__device__ __forceinline__ void fk_load_A(float* Asf, const float* __restrict__ A,
                                          int ldA, int m0, int K)
{
    int tid = threadIdx.x;
    int arow = tid >> 2, acol = (tid & 3) * 4;
#pragma unroll 4
    for (int k0 = 0; k0 < K; k0 += 16) {
        float4 v = *(const float4*)&A[(size_t)(m0 + arow) * ldA + k0 + acol];
        Asf[(k0 + acol + 0) * 68 + arow] = v.x;
        Asf[(k0 + acol + 1) * 68 + arow] = v.y;
        Asf[(k0 + acol + 2) * 68 + arow] = v.z;
        Asf[(k0 + acol + 3) * 68 + arow] = v.w;
    }
}
__device__ __forceinline__ void fk_load_W(float* Wsf, const float* __restrict__ W,
                                          int ldW, int n0, int K, bool transB)
{
    int tid = threadIdx.x;
    int wrow = tid >> 4, wcol = (tid & 15) * 4;
#pragma unroll 4
    for (int k0 = 0; k0 < K; k0 += 16) {
        if (transB) {
#pragma unroll
            for (int u = 0; u < 4; u++)
                Wsf[(k0 + wrow) * 64 + wcol + u] = W[(size_t)(n0 + wcol + u) * ldW + k0 + wrow];
        } else {
            *(float4*)&Wsf[(k0 + wrow) * 64 + wcol] =
                *(const float4*)&W[(size_t)(k0 + wrow) * ldW + n0 + wcol];
        }
    }
}
__device__ __forceinline__ void fk_compute(const float* Asf, const float* Wsf, int K,
                                           float c[4][4])
{
    int tid = threadIdx.x, tx = tid & 15, ty = tid >> 4;
#pragma unroll 16
    for (int kk = 0; kk < K; kk++) {
        float4 af = *(const float4*)&Asf[kk * 68 + ty * 4];
        float4 bf = *(const float4*)&Wsf[kk * 64 + tx * 4];
        float a4[4] = {af.x, af.y, af.z, af.w};
        float b4[4] = {bf.x, bf.y, bf.z, bf.w};
#pragma unroll
        for (int i = 0; i < 4; i++)
#pragma unroll
            for (int j = 0; j < 4; j++) c[i][j] = fmaf(a4[i], b4[j], c[i][j]);
    }
}

#define ASF_FLOATS (192 * 68)
#define WSF_FLOATS (192 * 64)
#define FK_SMEM  ((ASF_FLOATS + WSF_FLOATS) * 4)

// ---------------- K0: xp GEMM + weight folds ----------------
__global__ void __launch_bounds__(256) k0_comb(
    const float* __restrict__ x, const float* __restrict__ W_in, const float* __restrict__ b_in,
    const float* __restrict__ Wv_a, const float* __restrict__ Wo_a,
    const float* __restrict__ bv_a, const float* __restrict__ bo_a,
    const float* __restrict__ Wk_d, const float* __restrict__ Wq_d,
    const float* __restrict__ Wk_t, const float* __restrict__ Wq_t)
{
    extern __shared__ __align__(16) float sh[];
    float* Asf = sh;
    float* Wsf = sh + ASF_FLOATS;
    int blk = blockIdx.x, tid = threadIdx.x;

    const float* A; const float* W; const float* bias = nullptr; float* C;
    int ldA, ldW, m0, n0, K; bool transB = false;
    if (blk < 96) {
        A = x; ldA = MEL_; W = W_in; ldW = D_; bias = b_in; C = g_xp;
        m0 = (blk / 3) * 64; n0 = (blk % 3) * 64; K = MEL_;
    } else if (blk < 105) {
        int p = blk - 96;
        A = Wv_a; ldA = D_; W = Wo_a; ldW = D_; C = g_Wao;
        m0 = (p / 3) * 64; n0 = (p % 3) * 64; K = D_;
    } else if (blk < 114) {
        int p = blk - 105;
        A = Wk_d; ldA = D_; W = Wq_d; ldW = D_; C = g_Wkqd; transB = true;
        m0 = (p / 3) * 64; n0 = (p % 3) * 64; K = D_;
    } else if (blk < 123) {
        int p = blk - 114;
        A = Wk_t; ldA = D_; W = Wq_t; ldW = D_; C = g_Wkqt; transB = true;
        m0 = (p / 3) * 64; n0 = (p % 3) * 64; K = D_;
    } else {
        if (tid < D_) {
            float s = bo_a[tid];
#pragma unroll 8
            for (int e = 0; e < D_; e++) s = fmaf(bv_a[e], Wo_a[e * D_ + tid], s);
            g_bao[tid] = s;
        }
        return;
    }
    fk_load_A(Asf, A, ldA, m0, K);
    fk_load_W(Wsf, W, ldW, n0, K, transB);
    __syncthreads();
    float c[4][4] = {};
    fk_compute(Asf, Wsf, K, c);
    int tx = tid & 15, ty = tid >> 4;
#pragma unroll
    for (int i = 0; i < 4; i++) {
        int row = m0 + ty * 4 + i, col = n0 + tx * 4;
        float4 o; float* po = &o.x;
#pragma unroll
        for (int j = 0; j < 4; j++) {
            float v = c[i][j];
            if (bias) v += bias[col + j];
            po[j] = v;
        }
        *(float4*)&C[(size_t)row * D_ + col] = o;
    }
}

// ---------------- projKVQ ----------------
__global__ void __launch_bounds__(192) projKVQ(
    float* __restrict__ Ko, float* __restrict__ Vo, float* __restrict__ Qo,
    const float* __restrict__ A, const float* __restrict__ Wk,
    const float* __restrict__ Wv, const float* __restrict__ Wkq, int nUpd, int chunk)
{
    __shared__ float sa[D_];
    int blk = blockIdx.x;
    int b = blk / nUpd, i = blk % nUpd;
    int tid = threadIdx.x;
    sa[tid] = A[(size_t)(b * T_ + i * chunk) * D_ + tid];
    __syncthreads();
    if (tid < 144) {
        int gsel = tid / 48, q = tid % 48;
        const float* W = (gsel == 0) ? Wk : (gsel == 1) ? Wv : Wkq;
        float ax = 0.f, ay = 0.f, az = 0.f, aw = 0.f;
#pragma unroll 4
        for (int kk = 0; kk < D_; kk++) {
            float a = sa[kk];
            float4 w = *(const float4*)&W[kk * D_ + 4 * q];
            ax = fmaf(a, w.x, ax); ay = fmaf(a, w.y, ay);
            az = fmaf(a, w.z, az); aw = fmaf(a, w.w, aw);
        }
        float* O = (gsel == 0) ? Ko : (gsel == 1) ? Vo : Qo;
        float4 o = {ax, ay, az, aw};
        *(float4*)&O[(size_t)blk * D_ + 4 * q] = o;
    }
}

// ---------------- rec_d (+F fold) ----------------
__global__ void __launch_bounds__(256) rec_d_kernel(
    float* __restrict__ ERR, float* __restrict__ F,
    const float* __restrict__ Kmat, const float* __restrict__ Vmat,
    const float* __restrict__ Wao)
{
    __shared__ float sK[ND_][D_ + 1];
    __shared__ float sE[ND_][D_];
    __shared__ float Acf[ND_][ND_];
    int b = blockIdx.x, tid = threadIdx.x;
    for (int idx = tid; idx < ND_ * D_; idx += 256)
        sK[idx / D_][idx % D_] = Kmat[(size_t)b * ND_ * D_ + idx];
    __syncthreads();
    if (tid < 6) {
        const int pi[6] = {1, 2, 2, 3, 3, 3};
        const int pj[6] = {0, 0, 1, 0, 1, 2};
        int i = pi[tid], j = pj[tid];
        float s0 = 0.f, s1 = 0.f;
#pragma unroll 8
        for (int kk = 0; kk < D_; kk += 2) {
            s0 = fmaf(sK[j][kk],     sK[i][kk],     s0);
            s1 = fmaf(sK[j][kk + 1], sK[i][kk + 1], s1);
        }
        Acf[j][i] = cdv(i - 1 - j) * (s0 + s1);
    }
    __syncthreads();
    if (tid < D_) {
        float err[ND_];
#pragma unroll
        for (int i = 0; i < ND_; i++) {
            float s = Vmat[(size_t)(b * ND_ + i) * D_ + tid];
#pragma unroll
            for (int j = 0; j < i; j++) s -= Acf[j][i] * err[j];
            err[i] = s;
            sE[i][tid] = s;
            ERR[(size_t)(b * ND_ + i) * D_ + tid] = s;
        }
    }
    __syncthreads();
    if (tid < 192) {
        int j = tid / 48, q = tid % 48;
        float4 acc = *(float4*)&sE[j][4 * q];
#pragma unroll 4
        for (int e = 0; e < D_; e++) {
            float a = sE[j][e];
            float4 w = *(const float4*)&Wao[e * D_ + 4 * q];
            acc.x = fmaf(a, w.x, acc.x); acc.y = fmaf(a, w.y, acc.y);
            acc.z = fmaf(a, w.z, acc.z); acc.w = fmaf(a, w.w, acc.w);
        }
        *(float4*)&F[(size_t)(b * ND_ + j) * D_ + 4 * q] = acc;
    }
}

// ---------------- x2 fused: x2 = xp + xp@Wao + bao + alpha@F (full-K, alpha from smem) ----------------
__global__ void __launch_bounds__(256) x2_fused(
    const float* __restrict__ xp, const float* __restrict__ Wao, const float* __restrict__ bao,
    const float* __restrict__ Qd, const float* __restrict__ Fd, float* __restrict__ x2)
{
    extern __shared__ __align__(16) float sh[];
    float* Asf = sh;                       // xp tile transposed [192][68]
    float* Wsf = sh + ASF_FLOATS;          // Wao [192][64]
    float* sQ  = Wsf + WSF_FLOATS;         // [4*192]
    float* sF  = sQ + ND_ * D_;            // [4*192]
    float* alph = sF + ND_ * D_;           // [64][4]
    int blk = blockIdx.x;
    int m0 = (blk / 3) * 64, n0 = (blk % 3) * 64;
    int b = m0 >> 8;
    int tid = threadIdx.x, tx = tid & 15, ty = tid >> 4;

    fk_load_A(Asf, xp, D_, m0, D_);
    fk_load_W(Wsf, Wao, D_, n0, D_, false);
    for (int idx = tid; idx < ND_ * D_; idx += 256) {
        sQ[idx] = Qd[(size_t)b * ND_ * D_ + idx];
        sF[idx] = Fd[(size_t)b * ND_ * D_ + idx];
    }
    __syncthreads();
    float c[4][4] = {};
    fk_compute(Asf, Wsf, D_, c);
    // alpha from smem: thread (row=tid>>2, j=tid&3)
    {
        int row = tid >> 2, j = tid & 3;
        const float* qj = &sQ[j * D_];
        float s0 = 0.f, s1 = 0.f, s2 = 0.f, s3 = 0.f;
#pragma unroll 12
        for (int k = 0; k < D_; k += 4) {
            s0 = fmaf(Asf[(k + 0) * 68 + row], qj[k + 0], s0);
            s1 = fmaf(Asf[(k + 1) * 68 + row], qj[k + 1], s1);
            s2 = fmaf(Asf[(k + 2) * 68 + row], qj[k + 2], s2);
            s3 = fmaf(Asf[(k + 3) * 68 + row], qj[k + 3], s3);
        }
        float s = (s0 + s1) + (s2 + s3);
        int t = (m0 + row) & (T_ - 1), r = t >> 6;
        alph[row * 4 + j] = (j <= r) ? 0.5f * cdv(r - j) * s : 0.f;
    }
    __syncthreads();
#pragma unroll
    for (int i = 0; i < 4; i++) {
        int lrow = ty * 4 + i, row = m0 + lrow, col = n0 + tx * 4;
        float4 o; float* po = &o.x;
#pragma unroll
        for (int j = 0; j < 4; j++) {
            // xp residual from smem: xp[row][col+j] == Asf[(col+j)*68 + lrow]
            float v = c[i][j] + bao[col + j] + Asf[(col + j) * 68 + lrow];
#pragma unroll
            for (int jj = 0; jj < ND_; jj++)
                v = fmaf(alph[lrow * 4 + jj], sF[jj * D_ + col + j], v);
            po[j] = v;
        }
        *(float4*)&x2[(size_t)row * D_ + col] = o;
    }
}

// ---------------- glu_ln: LN1 in smem + full-K GLU GEMM ----------------
__global__ void __launch_bounds__(256) glu_ln(
    const float* __restrict__ x2, const float* __restrict__ g1, const float* __restrict__ b1,
    const float* __restrict__ W, const float* __restrict__ bias,
    const float* __restrict__ dw, const float* __restrict__ db,
    const float* __restrict__ bs, const float* __restrict__ bb, float* __restrict__ outp)
{
    extern __shared__ __align__(16) float sh[];
    float* Xs = sh;                        // [192][68] transposed x2 tile -> normalized
    float* Wa = Xs + ASF_FLOATS;           // [192][64]
    float* Wg = Wa + WSF_FLOATS;           // [192][64]
    float* pm = Wg + WSF_FLOATS;           // [4][64]
    float* pv = pm + 256;                  // [4][64]
    float* rowm = pv + 256;                // [64]
    float* rowr = rowm + 64;               // [64]
    int blk = blockIdx.x;
    int m0 = (blk / 3) * 64, n0 = (blk % 3) * 64;
    int tid = threadIdx.x, tx = tid & 15, ty = tid >> 4;

    fk_load_A(Xs, x2, D_, m0, D_);
    // load both W halves full-K
    {
        int wrow = tid >> 4, wcol = (tid & 15) * 4;
#pragma unroll 4
        for (int k0 = 0; k0 < D_; k0 += 16) {
            *(float4*)&Wa[(k0 + wrow) * 64 + wcol] =
                *(const float4*)&W[(size_t)(k0 + wrow) * D2_ + n0 + wcol];
            *(float4*)&Wg[(k0 + wrow) * 64 + wcol] =
                *(const float4*)&W[(size_t)(k0 + wrow) * D2_ + D_ + n0 + wcol];
        }
    }
    __syncthreads();
    // LN stats: 4 partials per row
    {
        int row = tid & 63, part = tid >> 6;
        float s = 0.f, s2 = 0.f;
#pragma unroll 8
        for (int k = part * 48; k < part * 48 + 48; k++) {
            float v = Xs[k * 68 + row]; s += v; s2 += v * v;
        }
        pm[part * 64 + row] = s; pv[part * 64 + row] = s2;
    }
    __syncthreads();
    if (tid < 64) {
        float ts  = pm[tid] + pm[64 + tid] + pm[128 + tid] + pm[192 + tid];
        float ts2 = pv[tid] + pv[64 + tid] + pv[128 + tid] + pv[192 + tid];
        float m = ts / D_;
        rowm[tid] = m;
        rowr[tid] = rsqrtf(ts2 / D_ - m * m + EPS_);
    }
    __syncthreads();
    for (int idx = tid; idx < D_ * 64; idx += 256) {
        int k = idx >> 6, r = idx & 63;
        Xs[k * 68 + r] = (Xs[k * 68 + r] - rowm[r]) * rowr[r] * g1[k] + b1[k];
    }
    __syncthreads();
    float cA[4][4] = {}, cG[4][4] = {};
#pragma unroll 8
    for (int kk = 0; kk < D_; kk++) {
        float4 af = *(const float4*)&Xs[kk * 68 + ty * 4];
        float4 ba = *(const float4*)&Wa[kk * 64 + tx * 4];
        float4 bg = *(const float4*)&Wg[kk * 64 + tx * 4];
        float a4[4] = {af.x, af.y, af.z, af.w};
        float p4[4] = {ba.x, ba.y, ba.z, ba.w};
        float q4[4] = {bg.x, bg.y, bg.z, bg.w};
#pragma unroll
        for (int i = 0; i < 4; i++)
#pragma unroll
            for (int j = 0; j < 4; j++) {
                cA[i][j] = fmaf(a4[i], p4[j], cA[i][j]);
                cG[i][j] = fmaf(a4[i], q4[j], cG[i][j]);
            }
    }
#pragma unroll
    for (int i = 0; i < 4; i++) {
        int row = m0 + ty * 4 + i, col = n0 + tx * 4;
        float4 o; float* po = &o.x;
#pragma unroll
        for (int j = 0; j < 4; j++) {
            float a = cA[i][j] + bias[col + j];
            float g = cG[i][j] + bias[D_ + col + j];
            float h = a * (1.f / (1.f + expf(-g)));
            h = h * dw[col + j] + db[col + j];
            h = h * bs[col + j] + bb[col + j];
            h = h * (1.f / (1.f + expf(-h)));
            po[j] = h;
        }
        *(float4*)&outp[(size_t)row * D_ + col] = o;
    }
}

// ---------------- pw2 GEMM (full-K, residual) ----------------
__global__ void __launch_bounds__(256) gemm_pw2(
    const float* __restrict__ A, const float* __restrict__ W,
    const float* __restrict__ bias, const float* __restrict__ res, float* __restrict__ C)
{
    extern __shared__ __align__(16) float sh[];
    float* Asf = sh;
    float* Wsf = sh + ASF_FLOATS;
    int blk = blockIdx.x;
    int m0 = (blk / 3) * 64, n0 = (blk % 3) * 64;
    int tid = threadIdx.x, tx = tid & 15, ty = tid >> 4;
    fk_load_A(Asf, A, D_, m0, D_);
    fk_load_W(Wsf, W, D_, n0, D_, false);
    __syncthreads();
    float c[4][4] = {};
    fk_compute(Asf, Wsf, D_, c);
#pragma unroll
    for (int i = 0; i < 4; i++) {
        int row = m0 + ty * 4 + i, col = n0 + tx * 4;
        float4 rv = *(const float4*)&res[(size_t)row * D_ + col];
        float4 o;
        o.x = c[i][0] + bias[col + 0] + rv.x;
        o.y = c[i][1] + bias[col + 1] + rv.y;
        o.z = c[i][2] + bias[col + 2] + rv.z;
        o.w = c[i][3] + bias[col + 3] + rv.w;
        *(float4*)&C[(size_t)row * D_ + col] = o;
    }
}

// ---------------- rec_t ----------------
__global__ void __launch_bounds__(256) rec_t_kernel(
    float* __restrict__ ERR, const float* __restrict__ Kmat, const float* __restrict__ Vmat)
{
    __shared__ float sK[NT_][D_ + 1];
    __shared__ float Acf[NT_][NT_];
    __shared__ float cd[NT_];
    int b = blockIdx.x, tid = threadIdx.x;
    if (tid < NT_) cd[tid] = cdv(tid);
    for (int idx = tid; idx < NT_ * D_; idx += 256)
        sK[idx / D_][idx % D_] = Kmat[(size_t)b * NT_ * D_ + idx];
    __syncthreads();
    const int NP = NT_ * (NT_ - 1) / 2;
    for (int p = tid; p < NP; p += 256) {
        int i = (int)((1.0f + sqrtf(1.0f + 8.0f * (float)p)) * 0.5f);
        while (i * (i - 1) / 2 > p) i--;
        while ((i + 1) * i / 2 <= p) i++;
        int j = p - i * (i - 1) / 2;
        float s0 = 0.f, s1 = 0.f;
#pragma unroll 8
        for (int kk = 0; kk < D_; kk += 2) {
            s0 = fmaf(sK[j][kk],     sK[i][kk],     s0);
            s1 = fmaf(sK[j][kk + 1], sK[i][kk + 1], s1);
        }
        Acf[j][i] = cd[i - 1 - j] * (s0 + s1);
    }
    __syncthreads();
    if (tid < D_) {
        float err[NT_];
#pragma unroll
        for (int i = 0; i < NT_; i++) {
            float a0 = 0.f, a1 = 0.f;
#pragma unroll
            for (int j = 0; j < i; j++) {
                if (j & 1) a1 = fmaf(Acf[j][i], err[j], a1);
                else       a0 = fmaf(Acf[j][i], err[j], a0);
            }
            err[i] = Vmat[(size_t)(b * NT_ + i) * D_ + tid] - a0 - a1;
            ERR[(size_t)(b * NT_ + i) * D_ + tid] = err[i];
        }
    }
}

// ---------------- qkfinal ----------------
__global__ void __launch_bounds__(192) qkfinal(
    const float* __restrict__ x3, const float* __restrict__ Kt, const float* __restrict__ Et,
    const float* __restrict__ g2, const float* __restrict__ b2, float* __restrict__ pp)
{
    extern __shared__ __align__(16) float sh[];
    float (*sKT)[33] = (float (*)[33])sh;
    float* sEt = sh + 192 * 33;
    float* red = sEt + NT_ * D_;
    float* alpha = red + 192;
    float* cd = alpha + 32;
    float* lred = cd + 32;
    int blk = blockIdx.x;
    int b = blk >> 4, tc = blk & 15, t0 = tc * 16;
    int tid = threadIdx.x;
    if (tid < NT_) cd[tid] = cdv(tid);
    for (int idx = tid; idx < NT_ * D_; idx += 192) {
        int j = idx / D_, e = idx % D_;
        sKT[e][j] = Kt[(size_t)(b * NT_ + j) * D_ + e];
        sEt[idx] = Et[(size_t)b * NT_ * D_ + idx];
    }
    __syncthreads();
    int j = tid & 31, g = tid >> 5;
    float ps = 0.f;
    for (int tt = 0; tt < 16; tt++) {
        int t = t0 + tt, row = b * T_ + t, r = t >> 3;
        {
            const float* qr = x3 + (size_t)row * D_;
            float part = 0.f;
#pragma unroll
            for (int u = 0; u < 32; u++) part = fmaf(qr[g * 32 + u], sKT[g * 32 + u][j], part);
            red[j * 6 + g] = part;
        }
        __syncthreads();
        if (tid < NT_) {
            float s = 0.f;
#pragma unroll
            for (int gg = 0; gg < 6; gg++) s += red[tid * 6 + gg];
            alpha[tid] = (tid <= r) ? cd[r - tid] * s : 0.f;
        }
        __syncthreads();
        float s = 0.f;
        for (int jj = 0; jj <= r; jj++) s = fmaf(alpha[jj], sEt[jj * D_ + tid], s);
        float x4 = x3[(size_t)row * D_ + tid] + 0.5f * s;
        float sm = x4, s2 = x4 * x4;
#pragma unroll
        for (int o = 16; o > 0; o >>= 1) {
            sm += __shfl_xor_sync(~0u, sm, o);
            s2 += __shfl_xor_sync(~0u, s2, o);
        }
        if ((tid & 31) == 0) { lred[tid >> 5] = sm; lred[6 + (tid >> 5)] = s2; }
        __syncthreads();
        float ts = 0.f, ts2 = 0.f;
#pragma unroll
        for (int i = 0; i < 6; i++) { ts += lred[i]; ts2 += lred[6 + i]; }
        float m = ts / D_;
        float var = ts2 / D_ - m * m;
        ps += (x4 - m) * rsqrtf(var + EPS_) * g2[tid] + b2[tid];
        __syncthreads();
    }
    pp[(size_t)(b * 16 + tc) * D_ + tid] = ps;
}

// ---------------- pool + classifier ----------------
__global__ void __launch_bounds__(192) poolcls(
    const float* __restrict__ pp, const float* __restrict__ Wc,
    const float* __restrict__ bc, float* __restrict__ out)
{
    __shared__ float pooled[D_];
    int b = blockIdx.x, tid = threadIdx.x;
    float s = 0.f;
#pragma unroll
    for (int q = 0; q < 16; q++) s += pp[(size_t)(b * 16 + q) * D_ + tid];
    pooled[tid] = s * (1.f / T_);
    __syncthreads();
    if (tid < NC_) {
        float acc = bc[tid];
#pragma unroll 8
        for (int e = 0; e < D_; e++) acc = fmaf(pooled[e], Wc[e * NC_ + tid], acc);
        out[b * NC_ + tid] = acc;
    }
}

// =====================================================================
extern "C" void kernel_launch(void* const* d_in, const int* in_sizes, int n_in,
                              void* d_out, int out_size)
{
    const float* x     = (const float*)d_in[0];
    const float* W_in  = (const float*)d_in[1];
    const float* b_in  = (const float*)d_in[2];
    const float* Wv_a  = (const float*)d_in[3];
    const float* bv_a  = (const float*)d_in[4];
    const float* Wo_a  = (const float*)d_in[5];
    const float* bo_a  = (const float*)d_in[6];
    const float* ln1_g = (const float*)d_in[7];
    const float* ln1_b = (const float*)d_in[8];
    const float* pw1_w = (const float*)d_in[9];
    const float* pw1_b = (const float*)d_in[10];
    const float* dw_w  = (const float*)d_in[11];
    const float* dw_b  = (const float*)d_in[12];
    const float* bn_s  = (const float*)d_in[13];
    const float* bn_b  = (const float*)d_in[14];
    const float* pw2_w = (const float*)d_in[15];
    const float* pw2_b = (const float*)d_in[16];
    const float* Wk_t  = (const float*)d_in[17];
    const float* Wv_t  = (const float*)d_in[18];
    const float* Wq_t  = (const float*)d_in[19];
    const float* Wk_d  = (const float*)d_in[20];
    const float* Wv_d  = (const float*)d_in[21];
    const float* Wq_d  = (const float*)d_in[22];
    const float* ln2_g = (const float*)d_in[23];
    const float* ln2_b = (const float*)d_in[24];
    const float* Wc    = (const float*)d_in[25];
    const float* bc    = (const float*)d_in[26];
    float* out = (float*)d_out;

    float *xp, *x2, *g2p, *x3, *Kd, *Vd, *Qd, *Ed, *Fd, *Kt, *Vt, *Qt, *Et;
    float *Wao, *bao, *Wkqd, *Wkqt, *pp;
    cudaGetSymbolAddress((void**)&xp,   g_xp);
    cudaGetSymbolAddress((void**)&x2,   g_x2);
    cudaGetSymbolAddress((void**)&g2p,  g_g2);
    cudaGetSymbolAddress((void**)&x3,   g_x3);
    cudaGetSymbolAddress((void**)&Kd,   g_Kd);
    cudaGetSymbolAddress((void**)&Vd,   g_Vd);
    cudaGetSymbolAddress((void**)&Qd,   g_Qd);
    cudaGetSymbolAddress((void**)&Ed,   g_Ed);
    cudaGetSymbolAddress((void**)&Fd,   g_Fd);
    cudaGetSymbolAddress((void**)&Kt,   g_Kt);
    cudaGetSymbolAddress((void**)&Vt,   g_Vt);
    cudaGetSymbolAddress((void**)&Qt,   g_Qt);
    cudaGetSymbolAddress((void**)&Et,   g_Et);
    cudaGetSymbolAddress((void**)&Wao,  g_Wao);
    cudaGetSymbolAddress((void**)&bao,  g_bao);
    cudaGetSymbolAddress((void**)&Wkqd, g_Wkqd);
    cudaGetSymbolAddress((void**)&Wkqt, g_Wkqt);
    cudaGetSymbolAddress((void**)&pp,   g_pp);

    const int X2_SMEM  = FK_SMEM + (ND_ * D_ * 2 + 256) * 4;
    const int GLU_SMEM = (ASF_FLOATS + 2 * WSF_FLOATS + 256 + 256 + 64 + 64) * 4;
    const int QKF_SMEM = (192 * 33 + NT_ * D_ + 192 + 32 + 32 + 12) * 4;
    cudaFuncSetAttribute(k0_comb,  cudaFuncAttributeMaxDynamicSharedMemorySize, FK_SMEM);
    cudaFuncSetAttribute(x2_fused, cudaFuncAttributeMaxDynamicSharedMemorySize, X2_SMEM);
    cudaFuncSetAttribute(glu_ln,   cudaFuncAttributeMaxDynamicSharedMemorySize, GLU_SMEM);
    cudaFuncSetAttribute(gemm_pw2, cudaFuncAttributeMaxDynamicSharedMemorySize, FK_SMEM);
    cudaFuncSetAttribute(qkfinal,  cudaFuncAttributeMaxDynamicSharedMemorySize, QKF_SMEM);

    k0_comb<<<124, 256, FK_SMEM>>>(x, W_in, b_in, Wv_a, Wo_a, bv_a, bo_a,
                                   Wk_d, Wq_d, Wk_t, Wq_t);
    projKVQ<<<B_ * ND_, 192>>>(Kd, Vd, Qd, xp, Wk_d, Wv_d, Wkqd, ND_, 64);
    rec_d_kernel<<<B_, 256>>>(Ed, Fd, Kd, Vd, Wao);
    x2_fused<<<96, 256, X2_SMEM>>>(xp, Wao, bao, Qd, Fd, x2);
    glu_ln<<<96, 256, GLU_SMEM>>>(x2, ln1_g, ln1_b, pw1_w, pw1_b, dw_w, dw_b, bn_s, bn_b, g2p);
    gemm_pw2<<<96, 256, FK_SMEM>>>(g2p, pw2_w, pw2_b, x2, x3);
    projKVQ<<<B_ * NT_, 192>>>(Kt, Vt, Qt, x3, Wk_t, Wv_t, Wkqt, NT_, 8);
    rec_t_kernel<<<B_, 256>>>(Et, Kt, Vt);
    qkfinal<<<B_ * 16, 192, QKF_SMEM>>>(x3, Qt, Et, ln2_g, ln2_b, pp);
    poolcls<<<B_, 192>>>(pp, Wc, bc, out);
}

// round 8
// speedup vs baseline: 1.1890x; 1.0076x over previous
#include <cuda_runtime.h>
#include <math.h>

#define B_   8
#define T_   256
#define MEL_ 128
#define D_   192
#define NC_  20
#define D2_  384
#define NT_  32
#define ND_  4
#define EPS_ 1e-5f

__device__ float g_xp [B_*T_*D_];
__device__ float g_x2 [B_*T_*D_];
__device__ float g_g2 [B_*T_*D_];
__device__ float g_x3 [B_*T_*D_];
__device__ float g_Kd [B_*ND_*D_];
__device__ float g_Vd [B_*ND_*D_];
__device__ float g_Qd [B_*ND_*D_];
__device__ float g_Ed [B_*ND_*D_];
__device__ float g_Fd [B_*ND_*D_];
__device__ float g_Kt [B_*NT_*D_];
__device__ float g_Vt [B_*NT_*D_];
__device__ float g_Qt [B_*NT_*D_];
__device__ float g_Et [B_*NT_*D_];
__device__ float g_Wao [D_*D_];
__device__ float g_bao [D_];
__device__ float g_Wkqd[D_*D_];
__device__ float g_Wkqt[D_*D_];
__device__ float g_pp [B_*16*D_];

__device__ __forceinline__ float cdv(int d) {
    const float L2A = -0.014499569695115089f;   // log2(0.99)
    const float L2E = -0.152003093445049970f;   // log2(0.90)
    float n = (float)(d + 1);
    return (exp2f(n * L2A) - exp2f(n * L2E)) * (0.1f / 0.09f);
}

// ---------------- full-K smem-resident GEMM pieces (256 threads, 64x64 tile) ----------------
// As layout: Asf[k*68 + row]  (transposed, padded stride 68)
// Ws layout: Wsf[k*64 + col]
__device__ __forceinline__ void fk_load_A(float* Asf, const float* __restrict__ A,
                                          int ldA, int m0, int K)
{
    int tid = threadIdx.x;
    int arow = tid >> 2, acol = (tid & 3) * 4;
#pragma unroll 4
    for (int k0 = 0; k0 < K; k0 += 16) {
        float4 v = *(const float4*)&A[(size_t)(m0 + arow) * ldA + k0 + acol];
        Asf[(k0 + acol + 0) * 68 + arow] = v.x;
        Asf[(k0 + acol + 1) * 68 + arow] = v.y;
        Asf[(k0 + acol + 2) * 68 + arow] = v.z;
        Asf[(k0 + acol + 3) * 68 + arow] = v.w;
    }
}
__device__ __forceinline__ void fk_load_W(float* Wsf, const float* __restrict__ W,
                                          int ldW, int n0, int K, bool transB)
{
    int tid = threadIdx.x;
    int wrow = tid >> 4, wcol = (tid & 15) * 4;
#pragma unroll 4
    for (int k0 = 0; k0 < K; k0 += 16) {
        if (transB) {
#pragma unroll
            for (int u = 0; u < 4; u++)
                Wsf[(k0 + wrow) * 64 + wcol + u] = W[(size_t)(n0 + wcol + u) * ldW + k0 + wrow];
        } else {
            *(float4*)&Wsf[(k0 + wrow) * 64 + wcol] =
                *(const float4*)&W[(size_t)(k0 + wrow) * ldW + n0 + wcol];
        }
    }
}

// manually software-pipelined mainloop: prefetch k+1 while computing k
template<int K>
__device__ __forceinline__ void fk_compute(const float* Asf, const float* Wsf, float c[4][4])
{
    int tid = threadIdx.x, tx = tid & 15, ty = tid >> 4;
    const float* pa = Asf + ty * 4;
    const float* pb = Wsf + tx * 4;
    float4 af = *(const float4*)pa;
    float4 bf = *(const float4*)pb;
#pragma unroll 4
    for (int kk = 0; kk < K - 1; kk++) {
        float4 afn = *(const float4*)(pa + (kk + 1) * 68);
        float4 bfn = *(const float4*)(pb + (kk + 1) * 64);
        float a4[4] = {af.x, af.y, af.z, af.w};
        float b4[4] = {bf.x, bf.y, bf.z, bf.w};
#pragma unroll
        for (int i = 0; i < 4; i++)
#pragma unroll
            for (int j = 0; j < 4; j++) c[i][j] = fmaf(a4[i], b4[j], c[i][j]);
        af = afn; bf = bfn;
    }
    {
        float a4[4] = {af.x, af.y, af.z, af.w};
        float b4[4] = {bf.x, bf.y, bf.z, bf.w};
#pragma unroll
        for (int i = 0; i < 4; i++)
#pragma unroll
            for (int j = 0; j < 4; j++) c[i][j] = fmaf(a4[i], b4[j], c[i][j]);
    }
}

#define ASF_FLOATS (192 * 68)
#define WSF_FLOATS (192 * 64)
#define FK_SMEM  ((ASF_FLOATS + WSF_FLOATS) * 4)

// ---------------- K0: xp GEMM + weight folds ----------------
__global__ void __launch_bounds__(256) k0_comb(
    const float* __restrict__ x, const float* __restrict__ W_in, const float* __restrict__ b_in,
    const float* __restrict__ Wv_a, const float* __restrict__ Wo_a,
    const float* __restrict__ bv_a, const float* __restrict__ bo_a,
    const float* __restrict__ Wk_d, const float* __restrict__ Wq_d,
    const float* __restrict__ Wk_t, const float* __restrict__ Wq_t)
{
    extern __shared__ __align__(16) float sh[];
    float* Asf = sh;
    float* Wsf = sh + ASF_FLOATS;
    int blk = blockIdx.x, tid = threadIdx.x;

    const float* A; const float* W; const float* bias = nullptr; float* C;
    int ldA, ldW, m0, n0, K; bool transB = false;
    if (blk < 96) {
        A = x; ldA = MEL_; W = W_in; ldW = D_; bias = b_in; C = g_xp;
        m0 = (blk / 3) * 64; n0 = (blk % 3) * 64; K = MEL_;
    } else if (blk < 105) {
        int p = blk - 96;
        A = Wv_a; ldA = D_; W = Wo_a; ldW = D_; C = g_Wao;
        m0 = (p / 3) * 64; n0 = (p % 3) * 64; K = D_;
    } else if (blk < 114) {
        int p = blk - 105;
        A = Wk_d; ldA = D_; W = Wq_d; ldW = D_; C = g_Wkqd; transB = true;
        m0 = (p / 3) * 64; n0 = (p % 3) * 64; K = D_;
    } else if (blk < 123) {
        int p = blk - 114;
        A = Wk_t; ldA = D_; W = Wq_t; ldW = D_; C = g_Wkqt; transB = true;
        m0 = (p / 3) * 64; n0 = (p % 3) * 64; K = D_;
    } else {
        if (tid < D_) {
            float s = bo_a[tid];
#pragma unroll 8
            for (int e = 0; e < D_; e++) s = fmaf(bv_a[e], Wo_a[e * D_ + tid], s);
            g_bao[tid] = s;
        }
        return;
    }
    fk_load_A(Asf, A, ldA, m0, K);
    fk_load_W(Wsf, W, ldW, n0, K, transB);
    __syncthreads();
    float c[4][4] = {};
    if (K == MEL_) fk_compute<MEL_>(Asf, Wsf, c);
    else           fk_compute<D_>(Asf, Wsf, c);
    int tx = tid & 15, ty = tid >> 4;
#pragma unroll
    for (int i = 0; i < 4; i++) {
        int row = m0 + ty * 4 + i, col = n0 + tx * 4;
        float4 o; float* po = &o.x;
#pragma unroll
        for (int j = 0; j < 4; j++) {
            float v = c[i][j];
            if (bias) v += bias[col + j];
            po[j] = v;
        }
        *(float4*)&C[(size_t)row * D_ + col] = o;
    }
}

// ---------------- projKVQ (deep-unrolled weight streaming) ----------------
__global__ void __launch_bounds__(192) projKVQ(
    float* __restrict__ Ko, float* __restrict__ Vo, float* __restrict__ Qo,
    const float* __restrict__ A, const float* __restrict__ Wk,
    const float* __restrict__ Wv, const float* __restrict__ Wkq, int nUpd, int chunk)
{
    __shared__ float sa[D_];
    int blk = blockIdx.x;
    int b = blk / nUpd, i = blk % nUpd;
    int tid = threadIdx.x;
    sa[tid] = A[(size_t)(b * T_ + i * chunk) * D_ + tid];
    __syncthreads();
    if (tid < 144) {
        int gsel = tid / 48, q = tid % 48;
        const float* W = (gsel == 0) ? Wk : (gsel == 1) ? Wv : Wkq;
        float ax = 0.f, ay = 0.f, az = 0.f, aw = 0.f;
#pragma unroll 16
        for (int kk = 0; kk < D_; kk++) {
            float a = sa[kk];
            float4 w = *(const float4*)&W[kk * D_ + 4 * q];
            ax = fmaf(a, w.x, ax); ay = fmaf(a, w.y, ay);
            az = fmaf(a, w.z, az); aw = fmaf(a, w.w, aw);
        }
        float* O = (gsel == 0) ? Ko : (gsel == 1) ? Vo : Qo;
        float4 o = {ax, ay, az, aw};
        *(float4*)&O[(size_t)blk * D_ + 4 * q] = o;
    }
}

// ---------------- rec_d (+F fold) ----------------
__global__ void __launch_bounds__(256) rec_d_kernel(
    float* __restrict__ ERR, float* __restrict__ F,
    const float* __restrict__ Kmat, const float* __restrict__ Vmat,
    const float* __restrict__ Wao)
{
    __shared__ float sK[ND_][D_ + 1];
    __shared__ float sE[ND_][D_];
    __shared__ float Acf[ND_][ND_];
    int b = blockIdx.x, tid = threadIdx.x;
    for (int idx = tid; idx < ND_ * D_; idx += 256)
        sK[idx / D_][idx % D_] = Kmat[(size_t)b * ND_ * D_ + idx];
    __syncthreads();
    if (tid < 6) {
        const int pi[6] = {1, 2, 2, 3, 3, 3};
        const int pj[6] = {0, 0, 1, 0, 1, 2};
        int i = pi[tid], j = pj[tid];
        float s0 = 0.f, s1 = 0.f;
#pragma unroll 8
        for (int kk = 0; kk < D_; kk += 2) {
            s0 = fmaf(sK[j][kk],     sK[i][kk],     s0);
            s1 = fmaf(sK[j][kk + 1], sK[i][kk + 1], s1);
        }
        Acf[j][i] = cdv(i - 1 - j) * (s0 + s1);
    }
    __syncthreads();
    if (tid < D_) {
        float err[ND_];
#pragma unroll
        for (int i = 0; i < ND_; i++) {
            float s = Vmat[(size_t)(b * ND_ + i) * D_ + tid];
#pragma unroll
            for (int j = 0; j < i; j++) s -= Acf[j][i] * err[j];
            err[i] = s;
            sE[i][tid] = s;
            ERR[(size_t)(b * ND_ + i) * D_ + tid] = s;
        }
    }
    __syncthreads();
    if (tid < 192) {
        int j = tid / 48, q = tid % 48;
        float4 acc = *(float4*)&sE[j][4 * q];
#pragma unroll 8
        for (int e = 0; e < D_; e++) {
            float a = sE[j][e];
            float4 w = *(const float4*)&Wao[e * D_ + 4 * q];
            acc.x = fmaf(a, w.x, acc.x); acc.y = fmaf(a, w.y, acc.y);
            acc.z = fmaf(a, w.z, acc.z); acc.w = fmaf(a, w.w, acc.w);
        }
        *(float4*)&F[(size_t)(b * ND_ + j) * D_ + 4 * q] = acc;
    }
}

// ---------------- x2 fused: x2 = xp + xp@Wao + bao + alpha@F ----------------
__global__ void __launch_bounds__(256) x2_fused(
    const float* __restrict__ xp, const float* __restrict__ Wao, const float* __restrict__ bao,
    const float* __restrict__ Qd, const float* __restrict__ Fd, float* __restrict__ x2)
{
    extern __shared__ __align__(16) float sh[];
    float* Asf = sh;                       // xp tile transposed [192][68]
    float* Wsf = sh + ASF_FLOATS;          // Wao [192][64]
    float* sQ  = Wsf + WSF_FLOATS;         // [4*192]
    float* sF  = sQ + ND_ * D_;            // [4*192]
    float* alph = sF + ND_ * D_;           // [64][4]
    int blk = blockIdx.x;
    int m0 = (blk / 3) * 64, n0 = (blk % 3) * 64;
    int b = m0 >> 8;
    int tid = threadIdx.x, tx = tid & 15, ty = tid >> 4;

    fk_load_A(Asf, xp, D_, m0, D_);
    fk_load_W(Wsf, Wao, D_, n0, D_, false);
    for (int idx = tid; idx < ND_ * D_; idx += 256) {
        sQ[idx] = Qd[(size_t)b * ND_ * D_ + idx];
        sF[idx] = Fd[(size_t)b * ND_ * D_ + idx];
    }
    __syncthreads();
    float c[4][4] = {};
    fk_compute<D_>(Asf, Wsf, c);
    {
        int row = tid >> 2, j = tid & 3;
        const float* qj = &sQ[j * D_];
        float s0 = 0.f, s1 = 0.f, s2 = 0.f, s3 = 0.f;
#pragma unroll 12
        for (int k = 0; k < D_; k += 4) {
            s0 = fmaf(Asf[(k + 0) * 68 + row], qj[k + 0], s0);
            s1 = fmaf(Asf[(k + 1) * 68 + row], qj[k + 1], s1);
            s2 = fmaf(Asf[(k + 2) * 68 + row], qj[k + 2], s2);
            s3 = fmaf(Asf[(k + 3) * 68 + row], qj[k + 3], s3);
        }
        float s = (s0 + s1) + (s2 + s3);
        int t = (m0 + row) & (T_ - 1), r = t >> 6;
        alph[row * 4 + j] = (j <= r) ? 0.5f * cdv(r - j) * s : 0.f;
    }
    __syncthreads();
#pragma unroll
    for (int i = 0; i < 4; i++) {
        int lrow = ty * 4 + i, row = m0 + lrow, col = n0 + tx * 4;
        float4 o; float* po = &o.x;
#pragma unroll
        for (int j = 0; j < 4; j++) {
            float v = c[i][j] + bao[col + j] + Asf[(col + j) * 68 + lrow];
#pragma unroll
            for (int jj = 0; jj < ND_; jj++)
                v = fmaf(alph[lrow * 4 + jj], sF[jj * D_ + col + j], v);
            po[j] = v;
        }
        *(float4*)&x2[(size_t)row * D_ + col] = o;
    }
}

// ---------------- glu_ln: LN1 in smem + full-K GLU GEMM (pipelined) ----------------
__global__ void __launch_bounds__(256) glu_ln(
    const float* __restrict__ x2, const float* __restrict__ g1, const float* __restrict__ b1,
    const float* __restrict__ W, const float* __restrict__ bias,
    const float* __restrict__ dw, const float* __restrict__ db,
    const float* __restrict__ bs, const float* __restrict__ bb, float* __restrict__ outp)
{
    extern __shared__ __align__(16) float sh[];
    float* Xs = sh;                        // [192][68]
    float* Wa = Xs + ASF_FLOATS;           // [192][64]
    float* Wg = Wa + WSF_FLOATS;           // [192][64]
    float* pm = Wg + WSF_FLOATS;           // [4][64]
    float* pv = pm + 256;
    float* rowm = pv + 256;
    float* rowr = rowm + 64;
    int blk = blockIdx.x;
    int m0 = (blk / 3) * 64, n0 = (blk % 3) * 64;
    int tid = threadIdx.x, tx = tid & 15, ty = tid >> 4;

    fk_load_A(Xs, x2, D_, m0, D_);
    {
        int wrow = tid >> 4, wcol = (tid & 15) * 4;
#pragma unroll 4
        for (int k0 = 0; k0 < D_; k0 += 16) {
            *(float4*)&Wa[(k0 + wrow) * 64 + wcol] =
                *(const float4*)&W[(size_t)(k0 + wrow) * D2_ + n0 + wcol];
            *(float4*)&Wg[(k0 + wrow) * 64 + wcol] =
                *(const float4*)&W[(size_t)(k0 + wrow) * D2_ + D_ + n0 + wcol];
        }
    }
    __syncthreads();
    {
        int row = tid & 63, part = tid >> 6;
        float s = 0.f, s2 = 0.f;
#pragma unroll 8
        for (int k = part * 48; k < part * 48 + 48; k++) {
            float v = Xs[k * 68 + row]; s += v; s2 += v * v;
        }
        pm[part * 64 + row] = s; pv[part * 64 + row] = s2;
    }
    __syncthreads();
    if (tid < 64) {
        float ts  = pm[tid] + pm[64 + tid] + pm[128 + tid] + pm[192 + tid];
        float ts2 = pv[tid] + pv[64 + tid] + pv[128 + tid] + pv[192 + tid];
        float m = ts / D_;
        rowm[tid] = m;
        rowr[tid] = rsqrtf(ts2 / D_ - m * m + EPS_);
    }
    __syncthreads();
    for (int idx = tid; idx < D_ * 64; idx += 256) {
        int k = idx >> 6, r = idx & 63;
        Xs[k * 68 + r] = (Xs[k * 68 + r] - rowm[r]) * rowr[r] * g1[k] + b1[k];
    }
    __syncthreads();
    float cA[4][4] = {}, cG[4][4] = {};
    {
        const float* pa = Xs + ty * 4;
        const float* pba = Wa + tx * 4;
        const float* pbg = Wg + tx * 4;
        float4 af = *(const float4*)pa;
        float4 ba = *(const float4*)pba;
        float4 bg = *(const float4*)pbg;
#pragma unroll 4
        for (int kk = 0; kk < D_ - 1; kk++) {
            float4 afn = *(const float4*)(pa + (kk + 1) * 68);
            float4 ban = *(const float4*)(pba + (kk + 1) * 64);
            float4 bgn = *(const float4*)(pbg + (kk + 1) * 64);
            float a4[4] = {af.x, af.y, af.z, af.w};
            float p4[4] = {ba.x, ba.y, ba.z, ba.w};
            float q4[4] = {bg.x, bg.y, bg.z, bg.w};
#pragma unroll
            for (int i = 0; i < 4; i++)
#pragma unroll
                for (int j = 0; j < 4; j++) {
                    cA[i][j] = fmaf(a4[i], p4[j], cA[i][j]);
                    cG[i][j] = fmaf(a4[i], q4[j], cG[i][j]);
                }
            af = afn; ba = ban; bg = bgn;
        }
        float a4[4] = {af.x, af.y, af.z, af.w};
        float p4[4] = {ba.x, ba.y, ba.z, ba.w};
        float q4[4] = {bg.x, bg.y, bg.z, bg.w};
#pragma unroll
        for (int i = 0; i < 4; i++)
#pragma unroll
            for (int j = 0; j < 4; j++) {
                cA[i][j] = fmaf(a4[i], p4[j], cA[i][j]);
                cG[i][j] = fmaf(a4[i], q4[j], cG[i][j]);
            }
    }
#pragma unroll
    for (int i = 0; i < 4; i++) {
        int row = m0 + ty * 4 + i, col = n0 + tx * 4;
        float4 o; float* po = &o.x;
#pragma unroll
        for (int j = 0; j < 4; j++) {
            float a = cA[i][j] + bias[col + j];
            float g = cG[i][j] + bias[D_ + col + j];
            float h = a * (1.f / (1.f + expf(-g)));
            h = h * dw[col + j] + db[col + j];
            h = h * bs[col + j] + bb[col + j];
            h = h * (1.f / (1.f + expf(-h)));
            po[j] = h;
        }
        *(float4*)&outp[(size_t)row * D_ + col] = o;
    }
}

// ---------------- pw2 GEMM (full-K pipelined, residual) ----------------
__global__ void __launch_bounds__(256) gemm_pw2(
    const float* __restrict__ A, const float* __restrict__ W,
    const float* __restrict__ bias, const float* __restrict__ res, float* __restrict__ C)
{
    extern __shared__ __align__(16) float sh[];
    float* Asf = sh;
    float* Wsf = sh + ASF_FLOATS;
    int blk = blockIdx.x;
    int m0 = (blk / 3) * 64, n0 = (blk % 3) * 64;
    int tid = threadIdx.x, tx = tid & 15, ty = tid >> 4;
    fk_load_A(Asf, A, D_, m0, D_);
    fk_load_W(Wsf, W, D_, n0, D_, false);
    __syncthreads();
    float c[4][4] = {};
    fk_compute<D_>(Asf, Wsf, c);
#pragma unroll
    for (int i = 0; i < 4; i++) {
        int row = m0 + ty * 4 + i, col = n0 + tx * 4;
        float4 rv = *(const float4*)&res[(size_t)row * D_ + col];
        float4 o;
        o.x = c[i][0] + bias[col + 0] + rv.x;
        o.y = c[i][1] + bias[col + 1] + rv.y;
        o.z = c[i][2] + bias[col + 2] + rv.z;
        o.w = c[i][3] + bias[col + 3] + rv.w;
        *(float4*)&C[(size_t)row * D_ + col] = o;
    }
}

// ---------------- rec_t ----------------
__global__ void __launch_bounds__(256) rec_t_kernel(
    float* __restrict__ ERR, const float* __restrict__ Kmat, const float* __restrict__ Vmat)
{
    __shared__ float sK[NT_][D_ + 1];
    __shared__ float Acf[NT_][NT_];
    __shared__ float cd[NT_];
    int b = blockIdx.x, tid = threadIdx.x;
    if (tid < NT_) cd[tid] = cdv(tid);
    for (int idx = tid; idx < NT_ * D_; idx += 256)
        sK[idx / D_][idx % D_] = Kmat[(size_t)b * NT_ * D_ + idx];
    __syncthreads();
    const int NP = NT_ * (NT_ - 1) / 2;
    for (int p = tid; p < NP; p += 256) {
        int i = (int)((1.0f + sqrtf(1.0f + 8.0f * (float)p)) * 0.5f);
        while (i * (i - 1) / 2 > p) i--;
        while ((i + 1) * i / 2 <= p) i++;
        int j = p - i * (i - 1) / 2;
        float s0 = 0.f, s1 = 0.f;
#pragma unroll 8
        for (int kk = 0; kk < D_; kk += 2) {
            s0 = fmaf(sK[j][kk],     sK[i][kk],     s0);
            s1 = fmaf(sK[j][kk + 1], sK[i][kk + 1], s1);
        }
        Acf[j][i] = cd[i - 1 - j] * (s0 + s1);
    }
    __syncthreads();
    if (tid < D_) {
        float err[NT_];
#pragma unroll
        for (int i = 0; i < NT_; i++) {
            float a0 = 0.f, a1 = 0.f;
#pragma unroll
            for (int j = 0; j < i; j++) {
                if (j & 1) a1 = fmaf(Acf[j][i], err[j], a1);
                else       a0 = fmaf(Acf[j][i], err[j], a0);
            }
            err[i] = Vmat[(size_t)(b * NT_ + i) * D_ + tid] - a0 - a1;
            ERR[(size_t)(b * NT_ + i) * D_ + tid] = err[i];
        }
    }
}

// ---------------- qkfinal ----------------
__global__ void __launch_bounds__(192) qkfinal(
    const float* __restrict__ x3, const float* __restrict__ Kt, const float* __restrict__ Et,
    const float* __restrict__ g2, const float* __restrict__ b2, float* __restrict__ pp)
{
    extern __shared__ __align__(16) float sh[];
    float (*sKT)[33] = (float (*)[33])sh;
    float* sEt = sh + 192 * 33;
    float* red = sEt + NT_ * D_;
    float* alpha = red + 192;
    float* cd = alpha + 32;
    float* lred = cd + 32;
    int blk = blockIdx.x;
    int b = blk >> 4, tc = blk & 15, t0 = tc * 16;
    int tid = threadIdx.x;
    if (tid < NT_) cd[tid] = cdv(tid);
    for (int idx = tid; idx < NT_ * D_; idx += 192) {
        int j = idx / D_, e = idx % D_;
        sKT[e][j] = Kt[(size_t)(b * NT_ + j) * D_ + e];
        sEt[idx] = Et[(size_t)b * NT_ * D_ + idx];
    }
    __syncthreads();
    int j = tid & 31, g = tid >> 5;
    float ps = 0.f;
    for (int tt = 0; tt < 16; tt++) {
        int t = t0 + tt, row = b * T_ + t, r = t >> 3;
        {
            const float* qr = x3 + (size_t)row * D_;
            float part = 0.f;
#pragma unroll
            for (int u = 0; u < 32; u++) part = fmaf(qr[g * 32 + u], sKT[g * 32 + u][j], part);
            red[j * 6 + g] = part;
        }
        __syncthreads();
        if (tid < NT_) {
            float s = 0.f;
#pragma unroll
            for (int gg = 0; gg < 6; gg++) s += red[tid * 6 + gg];
            alpha[tid] = (tid <= r) ? cd[r - tid] * s : 0.f;
        }
        __syncthreads();
        float s = 0.f;
        for (int jj = 0; jj <= r; jj++) s = fmaf(alpha[jj], sEt[jj * D_ + tid], s);
        float x4 = x3[(size_t)row * D_ + tid] + 0.5f * s;
        float sm = x4, s2 = x4 * x4;
#pragma unroll
        for (int o = 16; o > 0; o >>= 1) {
            sm += __shfl_xor_sync(~0u, sm, o);
            s2 += __shfl_xor_sync(~0u, s2, o);
        }
        if ((tid & 31) == 0) { lred[tid >> 5] = sm; lred[6 + (tid >> 5)] = s2; }
        __syncthreads();
        float ts = 0.f, ts2 = 0.f;
#pragma unroll
        for (int i = 0; i < 6; i++) { ts += lred[i]; ts2 += lred[6 + i]; }
        float m = ts / D_;
        float var = ts2 / D_ - m * m;
        ps += (x4 - m) * rsqrtf(var + EPS_) * g2[tid] + b2[tid];
        __syncthreads();
    }
    pp[(size_t)(b * 16 + tc) * D_ + tid] = ps;
}

// ---------------- pool + classifier ----------------
__global__ void __launch_bounds__(192) poolcls(
    const float* __restrict__ pp, const float* __restrict__ Wc,
    const float* __restrict__ bc, float* __restrict__ out)
{
    __shared__ float pooled[D_];
    int b = blockIdx.x, tid = threadIdx.x;
    float s = 0.f;
#pragma unroll
    for (int q = 0; q < 16; q++) s += pp[(size_t)(b * 16 + q) * D_ + tid];
    pooled[tid] = s * (1.f / T_);
    __syncthreads();
    if (tid < NC_) {
        float acc = bc[tid];
#pragma unroll 8
        for (int e = 0; e < D_; e++) acc = fmaf(pooled[e], Wc[e * NC_ + tid], acc);
        out[b * NC_ + tid] = acc;
    }
}

// =====================================================================
extern "C" void kernel_launch(void* const* d_in, const int* in_sizes, int n_in,
                              void* d_out, int out_size)
{
    const float* x     = (const float*)d_in[0];
    const float* W_in  = (const float*)d_in[1];
    const float* b_in  = (const float*)d_in[2];
    const float* Wv_a  = (const float*)d_in[3];
    const float* bv_a  = (const float*)d_in[4];
    const float* Wo_a  = (const float*)d_in[5];
    const float* bo_a  = (const float*)d_in[6];
    const float* ln1_g = (const float*)d_in[7];
    const float* ln1_b = (const float*)d_in[8];
    const float* pw1_w = (const float*)d_in[9];
    const float* pw1_b = (const float*)d_in[10];
    const float* dw_w  = (const float*)d_in[11];
    const float* dw_b  = (const float*)d_in[12];
    const float* bn_s  = (const float*)d_in[13];
    const float* bn_b  = (const float*)d_in[14];
    const float* pw2_w = (const float*)d_in[15];
    const float* pw2_b = (const float*)d_in[16];
    const float* Wk_t  = (const float*)d_in[17];
    const float* Wv_t  = (const float*)d_in[18];
    const float* Wq_t  = (const float*)d_in[19];
    const float* Wk_d  = (const float*)d_in[20];
    const float* Wv_d  = (const float*)d_in[21];
    const float* Wq_d  = (const float*)d_in[22];
    const float* ln2_g = (const float*)d_in[23];
    const float* ln2_b = (const float*)d_in[24];
    const float* Wc    = (const float*)d_in[25];
    const float* bc    = (const float*)d_in[26];
    float* out = (float*)d_out;

    float *xp, *x2, *g2p, *x3, *Kd, *Vd, *Qd, *Ed, *Fd, *Kt, *Vt, *Qt, *Et;
    float *Wao, *bao, *Wkqd, *Wkqt, *pp;
    cudaGetSymbolAddress((void**)&xp,   g_xp);
    cudaGetSymbolAddress((void**)&x2,   g_x2);
    cudaGetSymbolAddress((void**)&g2p,  g_g2);
    cudaGetSymbolAddress((void**)&x3,   g_x3);
    cudaGetSymbolAddress((void**)&Kd,   g_Kd);
    cudaGetSymbolAddress((void**)&Vd,   g_Vd);
    cudaGetSymbolAddress((void**)&Qd,   g_Qd);
    cudaGetSymbolAddress((void**)&Ed,   g_Ed);
    cudaGetSymbolAddress((void**)&Fd,   g_Fd);
    cudaGetSymbolAddress((void**)&Kt,   g_Kt);
    cudaGetSymbolAddress((void**)&Vt,   g_Vt);
    cudaGetSymbolAddress((void**)&Qt,   g_Qt);
    cudaGetSymbolAddress((void**)&Et,   g_Et);
    cudaGetSymbolAddress((void**)&Wao,  g_Wao);
    cudaGetSymbolAddress((void**)&bao,  g_bao);
    cudaGetSymbolAddress((void**)&Wkqd, g_Wkqd);
    cudaGetSymbolAddress((void**)&Wkqt, g_Wkqt);
    cudaGetSymbolAddress((void**)&pp,   g_pp);

    const int X2_SMEM  = FK_SMEM + (ND_ * D_ * 2 + 256) * 4;
    const int GLU_SMEM = (ASF_FLOATS + 2 * WSF_FLOATS + 256 + 256 + 64 + 64) * 4;
    const int QKF_SMEM = (192 * 33 + NT_ * D_ + 192 + 32 + 32 + 12) * 4;
    cudaFuncSetAttribute(k0_comb,  cudaFuncAttributeMaxDynamicSharedMemorySize, FK_SMEM);
    cudaFuncSetAttribute(x2_fused, cudaFuncAttributeMaxDynamicSharedMemorySize, X2_SMEM);
    cudaFuncSetAttribute(glu_ln,   cudaFuncAttributeMaxDynamicSharedMemorySize, GLU_SMEM);
    cudaFuncSetAttribute(gemm_pw2, cudaFuncAttributeMaxDynamicSharedMemorySize, FK_SMEM);
    cudaFuncSetAttribute(qkfinal,  cudaFuncAttributeMaxDynamicSharedMemorySize, QKF_SMEM);

    k0_comb<<<124, 256, FK_SMEM>>>(x, W_in, b_in, Wv_a, Wo_a, bv_a, bo_a,
                                   Wk_d, Wq_d, Wk_t, Wq_t);
    projKVQ<<<B_ * ND_, 192>>>(Kd, Vd, Qd, xp, Wk_d, Wv_d, Wkqd, ND_, 64);
    rec_d_kernel<<<B_, 256>>>(Ed, Fd, Kd, Vd, Wao);
    x2_fused<<<96, 256, X2_SMEM>>>(xp, Wao, bao, Qd, Fd, x2);
    glu_ln<<<96, 256, GLU_SMEM>>>(x2, ln1_g, ln1_b, pw1_w, pw1_b, dw_w, dw_b, bn_s, bn_b, g2p);
    gemm_pw2<<<96, 256, FK_SMEM>>>(g2p, pw2_w, pw2_b, x2, x3);
    projKVQ<<<B_ * NT_, 192>>>(Kt, Vt, Qt, x3, Wk_t, Wv_t, Wkqt, NT_, 8);
    rec_t_kernel<<<B_, 256>>>(Et, Kt, Vt);
    qkfinal<<<B_ * 16, 192, QKF_SMEM>>>(x3, Qt, Et, ln2_g, ln2_b, pp);
    poolcls<<<B_, 192>>>(pp, Wc, bc, out);
}